// round 1
// baseline (speedup 1.0000x reference)
#include <cuda_runtime.h>
#include <math.h>

// Problem constants
#define BB   2
#define SQ   1024
#define DIM  512
#define NH   8
#define DKH  64
#define NL   6
#define DFF  2048
#define NV   32000
#define MAXS 1025   // MAXSEQ+1

// ---------------- device scratch (no allocations allowed) ----------------
__device__ float g_x [BB*SQ*DIM];
__device__ float g_h [BB*SQ*DIM];
__device__ float g_q [BB*SQ*DIM];
__device__ float g_k [BB*SQ*DIM];
__device__ float g_v [BB*SQ*DIM];
__device__ float g_rb[BB*NH*SQ];
__device__ float g_sc[(long long)BB*NH*SQ*SQ];   // 67 MB
__device__ float g_at[BB*SQ*DIM];
__device__ float g_ff[BB*SQ*DFF];

// ---------------- generic tiled SGEMM ----------------
// C[m,n] = sum_k A[m,k] * B[n,k]   (BNT=true,  both row-major, K contiguous)
// C[m,n] = sum_k A[m,k] * B[k,n]   (BNT=false, B row-major [K,N])
// BM=128, BN=64, BK=16, 256 threads, each thread 8x4 outputs.

struct GP {
    const float* A; const float* B; const float* bias;
    const float* resid; const float* rbias; const int* mask;
    float* C;
    int M, N, K;
    long long Az, Bz, Cz;
    float scale;
};

enum { M_PLAIN = 0, M_QKV, M_RESID, M_RELU, M_SCORES, M_PV };

template<int MODE, bool BNT>
__global__ __launch_bounds__(256) void gemm_k(GP p) {
    __shared__ float As[16][132];   // [k][m], padded, 16B-aligned rows
    __shared__ float Bs[16][68];    // [k][n]

    const int t  = threadIdx.x;
    const int tx = t & 15;
    const int ty = t >> 4;
    const int n0 = blockIdx.x * 64;
    const int m0 = blockIdx.y * 128;
    const int z  = blockIdx.z;

    const float* A = p.A + (long long)z * p.Az;
    const float* B = p.B + (long long)z * p.Bz;

    float acc[8][4];
#pragma unroll
    for (int i = 0; i < 8; ++i)
#pragma unroll
        for (int j = 0; j < 4; ++j) acc[i][j] = 0.f;

    for (int k0 = 0; k0 < p.K; k0 += 16) {
        // load A tile 128x16 (2 float4 per thread), store transposed
#pragma unroll
        for (int it = 0; it < 2; ++it) {
            int idx = t + it * 256;
            int r   = idx >> 2;
            int c4  = (idx & 3) * 4;
            float4 v = *(const float4*)(A + (long long)(m0 + r) * p.K + k0 + c4);
            As[c4 + 0][r] = v.x; As[c4 + 1][r] = v.y;
            As[c4 + 2][r] = v.z; As[c4 + 3][r] = v.w;
        }
        // load B tile
        if (BNT) {
            int r  = t >> 2;
            int c4 = (t & 3) * 4;
            float4 v = *(const float4*)(B + (long long)(n0 + r) * p.K + k0 + c4);
            Bs[c4 + 0][r] = v.x; Bs[c4 + 1][r] = v.y;
            Bs[c4 + 2][r] = v.z; Bs[c4 + 3][r] = v.w;
        } else {
            int r = t >> 4;          // k within tile
            int c = (t & 15) * 4;    // n within tile
            float4 v = *(const float4*)(B + (long long)(k0 + r) * p.N + n0 + c);
            *(float4*)&Bs[r][c] = v;
        }
        __syncthreads();

#pragma unroll
        for (int k = 0; k < 16; ++k) {
            float4 a0 = *(const float4*)&As[k][ty * 8];
            float4 a1 = *(const float4*)&As[k][ty * 8 + 4];
            float4 b4 = *(const float4*)&Bs[k][tx * 4];
            float am[8] = {a0.x, a0.y, a0.z, a0.w, a1.x, a1.y, a1.z, a1.w};
            float bn[4] = {b4.x, b4.y, b4.z, b4.w};
#pragma unroll
            for (int i = 0; i < 8; ++i)
#pragma unroll
                for (int j = 0; j < 4; ++j) acc[i][j] += am[i] * bn[j];
        }
        __syncthreads();
    }

    // epilogue
#pragma unroll
    for (int i = 0; i < 8; ++i) {
        int m = m0 + ty * 8 + i;
#pragma unroll
        for (int j = 0; j < 4; ++j) {
            int n = n0 + tx * 4 + j;
            float v = acc[i][j];
            if (MODE == M_PLAIN) {
                p.C[(long long)m * p.N + n] = v + p.bias[n];
            } else if (MODE == M_QKV) {
                float o = v + p.bias[n];
                int b = m >> 10, s = m & (SQ - 1);
                int h = n >> 6,  dk = n & 63;
                p.C[(((long long)(b * NH + h)) * SQ + s) * DKH + dk] = o;
            } else if (MODE == M_RESID) {
                long long idx = (long long)m * p.N + n;
                p.C[idx] = p.resid[idx] + v + p.bias[n];
            } else if (MODE == M_RELU) {
                float o = v + p.bias[n];
                p.C[(long long)m * p.N + n] = o > 0.f ? o : 0.f;
            } else if (MODE == M_SCORES) {
                int b = z >> 3;
                int mk = p.mask[((long long)b * SQ + m) * SQ + n];
                float o = v * p.scale + p.rbias[z * SQ + n];
                p.C[(long long)z * p.Cz + (long long)m * SQ + n] = mk ? o : -1e9f;
            } else if (MODE == M_PV) {
                int b = z >> 3, h = z & 7;
                p.C[((long long)(b * SQ + m)) * DIM + h * DKH + n] = v;
            }
        }
    }
}

// ---------------- embedding + sinusoidal PE ----------------
__global__ void embed_k(const int* inp, const float* emb, float* x) {
    int row = blockIdx.x;           // b*SQ + s
    int s   = row & (SQ - 1);
    int tok = inp[row];
    const float* e = emb + (long long)tok * DIM;
    const float ln10k_over_d = 9.210340371976184f / (float)DIM;
    for (int d = threadIdx.x; d < DIM; d += 256) {
        int   i2  = d & ~1;
        float dv  = expf(-(float)i2 * ln10k_over_d);
        float arg = (float)s * dv;
        float pe  = (d & 1) ? cosf(arg) : sinf(arg);
        x[(long long)row * DIM + d] = e[d] * 22.62741699796952f + pe;
    }
}

// ---------------- layernorm (ddof=1, /(std+eps)) ----------------
__global__ void ln_k(const float* x, const float* ga, const float* be, float* y) {
    int row = blockIdx.x;
    const float* xr = x + (long long)row * DIM;
    float* yr = y + (long long)row * DIM;
    __shared__ float red[256];
    int t = threadIdx.x;
    float v0 = xr[t], v1 = xr[t + 256];
    red[t] = v0 + v1;
    __syncthreads();
    for (int o = 128; o > 0; o >>= 1) { if (t < o) red[t] += red[t + o]; __syncthreads(); }
    float mean = red[0] * (1.f / (float)DIM);
    __syncthreads();
    float d0 = v0 - mean, d1 = v1 - mean;
    red[t] = d0 * d0 + d1 * d1;
    __syncthreads();
    for (int o = 128; o > 0; o >>= 1) { if (t < o) red[t] += red[t + o]; __syncthreads(); }
    float stdv = sqrtf(red[0] / (float)(DIM - 1));
    float inv  = 1.f / (stdv + 1e-6f);
    yr[t]       = ga[t] * d0 * inv + be[t];
    yr[t + 256] = ga[t + 256] * d1 * inv + be[t + 256];
}

// ---------------- relative bias: r[b,h,k] = scale * dot(q[b,h,k], pe[h,k]) ----
__global__ void relbias_k(const float* q, const float* rel, float* r) {
    int idx  = blockIdx.x * 8 + (threadIdx.x >> 5);   // (b*NH+h)*SQ + k
    int lane = threadIdx.x & 31;
    int k = idx & (SQ - 1);
    int h = (idx >> 10) & (NH - 1);
    const float* qp = q   + (long long)idx * DKH;
    const float* pp = rel + ((long long)h * MAXS + k) * DKH;
    float d = qp[lane] * pp[lane] + qp[lane + 32] * pp[lane + 32];
    for (int o = 16; o > 0; o >>= 1) d += __shfl_xor_sync(0xffffffffu, d, o);
    if (lane == 0) r[idx] = d * 0.125f;
}

// ---------------- row softmax over S=1024 (in place) ----------------
__global__ void softmax_k(float* sc) {
    float* s = sc + (long long)blockIdx.x * SQ;
    __shared__ float red[256];
    int t = threadIdx.x;
    float mx = -1e30f;
    for (int k = t; k < SQ; k += 256) mx = fmaxf(mx, s[k]);
    red[t] = mx; __syncthreads();
    for (int o = 128; o > 0; o >>= 1) { if (t < o) red[t] = fmaxf(red[t], red[t + o]); __syncthreads(); }
    mx = red[0]; __syncthreads();
    float sum = 0.f;
    for (int k = t; k < SQ; k += 256) { float e = expf(s[k] - mx); s[k] = e; sum += e; }
    red[t] = sum; __syncthreads();
    for (int o = 128; o > 0; o >>= 1) { if (t < o) red[t] += red[t + o]; __syncthreads(); }
    float inv = 1.f / red[0];
    __syncthreads();
    for (int k = t; k < SQ; k += 256) s[k] *= inv;
}

// ---------------- log_softmax over vocab (in place on d_out) ----------------
__global__ void logsoftmax_k(float* out) {
    float* r = out + (long long)blockIdx.x * NV;
    __shared__ float red[256];
    int t = threadIdx.x;
    float mx = -1e30f;
    for (int k = t; k < NV; k += 256) mx = fmaxf(mx, r[k]);
    red[t] = mx; __syncthreads();
    for (int o = 128; o > 0; o >>= 1) { if (t < o) red[t] = fmaxf(red[t], red[t + o]); __syncthreads(); }
    mx = red[0]; __syncthreads();
    float sum = 0.f;
    for (int k = t; k < NV; k += 256) sum += expf(r[k] - mx);
    red[t] = sum; __syncthreads();
    for (int o = 128; o > 0; o >>= 1) { if (t < o) red[t] += red[t + o]; __syncthreads(); }
    float lse = mx + logf(red[0]);
    __syncthreads();
    for (int k = t; k < NV; k += 256) r[k] -= lse;
}

// ---------------- host driver ----------------
static inline GP mkgp(const float* A, const float* B, const float* bias, float* C,
                      int M, int N, int K) {
    GP p; p.A = A; p.B = B; p.bias = bias; p.C = C;
    p.resid = nullptr; p.rbias = nullptr; p.mask = nullptr;
    p.M = M; p.N = N; p.K = K; p.Az = 0; p.Bz = 0; p.Cz = 0; p.scale = 1.f;
    return p;
}

extern "C" void kernel_launch(void* const* d_in, const int* in_sizes, int n_in,
                              void* d_out, int out_size) {
    const int*   inp   = (const int*)  d_in[0];
    const int*   mask  = (const int*)  d_in[1];
    const float* emb   = (const float*)d_in[2];
    const float* Wq    = (const float*)d_in[3];
    const float* bq    = (const float*)d_in[4];
    const float* Wk    = (const float*)d_in[5];
    const float* bk    = (const float*)d_in[6];
    const float* Wv    = (const float*)d_in[7];
    const float* bv    = (const float*)d_in[8];
    const float* Wo    = (const float*)d_in[9];
    const float* bo    = (const float*)d_in[10];
    const float* rel   = (const float*)d_in[11];
    const float* ln1a  = (const float*)d_in[12];
    const float* ln1b  = (const float*)d_in[13];
    const float* ln2a  = (const float*)d_in[14];
    const float* ln2b  = (const float*)d_in[15];
    const float* W1    = (const float*)d_in[16];
    const float* b1    = (const float*)d_in[17];
    const float* W2    = (const float*)d_in[18];
    const float* b2    = (const float*)d_in[19];
    const float* lnfa  = (const float*)d_in[20];
    const float* lnfb  = (const float*)d_in[21];
    const float* Wg    = (const float*)d_in[22];
    const float* bg    = (const float*)d_in[23];
    float* out = (float*)d_out;

    float *x, *h, *q, *k_, *v, *rb, *sc, *at, *ff;
    cudaGetSymbolAddress((void**)&x,  g_x);
    cudaGetSymbolAddress((void**)&h,  g_h);
    cudaGetSymbolAddress((void**)&q,  g_q);
    cudaGetSymbolAddress((void**)&k_, g_k);
    cudaGetSymbolAddress((void**)&v,  g_v);
    cudaGetSymbolAddress((void**)&rb, g_rb);
    cudaGetSymbolAddress((void**)&sc, g_sc);
    cudaGetSymbolAddress((void**)&at, g_at);
    cudaGetSymbolAddress((void**)&ff, g_ff);

    const int Mtok = BB * SQ;   // 2048

    embed_k<<<Mtok, 256>>>(inp, emb, x);

    for (int l = 0; l < NL; ++l) {
        const long long wOff = (long long)l * DIM * DIM;

        ln_k<<<Mtok, 256>>>(x, ln1a + l * DIM, ln1b + l * DIM, h);

        // QKV projections, scattered to [B,H,S,DK]
        {
            dim3 g(DIM / 64, Mtok / 128, 1);
            GP pq = mkgp(h, Wq + wOff, bq + l * DIM, q,  Mtok, DIM, DIM);
            GP pk = mkgp(h, Wk + wOff, bk + l * DIM, k_, Mtok, DIM, DIM);
            GP pv = mkgp(h, Wv + wOff, bv + l * DIM, v,  Mtok, DIM, DIM);
            gemm_k<M_QKV, true><<<g, 256>>>(pq);
            gemm_k<M_QKV, true><<<g, 256>>>(pk);
            gemm_k<M_QKV, true><<<g, 256>>>(pv);
        }

        relbias_k<<<BB * NH * SQ / 8, 256>>>(q, rel + (long long)l * NH * MAXS * DKH, rb);

        // scores = scale*(q·k) + r[k], masked
        {
            GP p = mkgp(q, k_, nullptr, sc, SQ, SQ, DKH);
            p.Az = (long long)SQ * DKH; p.Bz = (long long)SQ * DKH;
            p.Cz = (long long)SQ * SQ;
            p.rbias = rb; p.mask = mask; p.scale = 0.125f;
            dim3 g(SQ / 64, SQ / 128, BB * NH);
            gemm_k<M_SCORES, true><<<g, 256>>>(p);
        }

        softmax_k<<<BB * NH * SQ, 256>>>(sc);

        // attn = P @ V, scattered back to [B,S,D]
        {
            GP p = mkgp(sc, v, nullptr, at, SQ, DKH, SQ);
            p.Az = (long long)SQ * SQ; p.Bz = (long long)SQ * DKH;
            dim3 g(1, SQ / 128, BB * NH);
            gemm_k<M_PV, false><<<g, 256>>>(p);
        }

        // x = x + attn @ Wo^T + bo
        {
            GP p = mkgp(at, Wo + wOff, bo + l * DIM, x, Mtok, DIM, DIM);
            p.resid = x;
            dim3 g(DIM / 64, Mtok / 128, 1);
            gemm_k<M_RESID, true><<<g, 256>>>(p);
        }

        ln_k<<<Mtok, 256>>>(x, ln2a + l * DIM, ln2b + l * DIM, h);

        // ffn = relu(h @ W1^T + b1)
        {
            GP p = mkgp(h, W1 + (long long)l * DFF * DIM, b1 + l * DFF, ff, Mtok, DFF, DIM);
            dim3 g(DFF / 64, Mtok / 128, 1);
            gemm_k<M_RELU, true><<<g, 256>>>(p);
        }
        // x = x + ffn @ W2^T + b2
        {
            GP p = mkgp(ff, W2 + (long long)l * DIM * DFF, b2 + l * DIM, x, Mtok, DIM, DFF);
            p.resid = x;
            dim3 g(DIM / 64, Mtok / 128, 1);
            gemm_k<M_RESID, true><<<g, 256>>>(p);
        }
    }

    ln_k<<<Mtok, 256>>>(x, lnfa, lnfb, h);

    // logits = h @ Wg^T + bg  ->  d_out
    {
        GP p = mkgp(h, Wg, bg, out, Mtok, NV, DIM);
        dim3 g(NV / 64, Mtok / 128, 1);
        gemm_k<M_PLAIN, true><<<g, 256>>>(p);
    }

    logsoftmax_k<<<Mtok, 256>>>(out);
}

// round 2
// speedup vs baseline: 1.4261x; 1.4261x over previous
#include <cuda_runtime.h>
#include <math.h>

// Problem constants
#define BB   2
#define SQ   1024
#define DIM  512
#define NH   8
#define DKH  64
#define NL   6
#define DFF  2048
#define NV   32000
#define MAXS 1025   // MAXSEQ+1

// ---------------- device scratch (no allocations allowed) ----------------
__device__ float g_x [BB*SQ*DIM];
__device__ float g_h [BB*SQ*DIM];
__device__ float g_q [BB*SQ*DIM];
__device__ float g_k [BB*SQ*DIM];
__device__ float g_v [BB*SQ*DIM];
__device__ float g_rb[BB*NH*SQ];
__device__ float g_sc[(long long)BB*NH*SQ*SQ];   // 67 MB
__device__ float g_at[BB*SQ*DIM];
__device__ float g_ff[BB*SQ*DFF];

struct GP {
    const float* A; const float* B; const float* bias;
    const float* resid; const float* rbias; const int* mask;
    float* C;
    int M, N, K;
    long long Az, Bz, Cz;
    float scale;
};

enum { M_PLAIN = 0, M_QKV, M_RESID, M_RELU, M_SCORES, M_PV };

__device__ __forceinline__ unsigned f2tf(float f) {
    unsigned r;
    asm("cvt.rna.tf32.f32 %0, %1;" : "=r"(r) : "f"(f));
    return r;
}

__device__ __forceinline__ void mma8(float* c, const unsigned* a, unsigned b0, unsigned b1) {
    asm volatile(
        "mma.sync.aligned.m16n8k8.row.col.f32.tf32.tf32.f32 "
        "{%0,%1,%2,%3},{%4,%5,%6,%7},{%8,%9},{%0,%1,%2,%3};"
        : "+f"(c[0]), "+f"(c[1]), "+f"(c[2]), "+f"(c[3])
        : "r"(a[0]), "r"(a[1]), "r"(a[2]), "r"(a[3]), "r"(b0), "r"(b1));
}

// ---------------- TF32 tensor-core GEMM ----------------
// BM=128, BK=16, BN template (64 or 128). 256 threads = 8 warps as 4(m)x2(n).
// Warp tile 32 x (BN/2). mma m16n8k8 tf32, fp32 accumulate.
// BNT=true:  C[m,n] = sum_k A[m,k] * B[n,k]  (both row-major, K contiguous)
// BNT=false: C[m,n] = sum_k A[m,k] * B[k,n]  (B row-major [K,N], BN must be 64)
template<int MODE, bool BNT, int BN>
__global__ __launch_bounds__(256) void mma_k(GP p) {
    constexpr int WN   = BN / 2;      // per-warp n extent
    constexpr int NTN  = WN / 8;      // n8 sub-tiles per warp
    constexpr int BPAD = BN + 8;      // pad%32==8 -> conflict-free frag LDS
    constexpr int NLB  = (BN == 128) ? 2 : 1;

    __shared__ unsigned As[16][136];
    __shared__ unsigned Bs[16][BPAD];

    const int t    = threadIdx.x;
    const int lane = t & 31;
    const int warp = t >> 5;
    const int wm   = warp >> 1;       // 0..3
    const int wn   = warp & 1;        // 0..1
    const int n0   = blockIdx.x * BN;
    const int m0   = blockIdx.y * 128;
    const int z    = blockIdx.z;

    const float* A = p.A + (long long)z * p.Az;
    const float* B = p.B + (long long)z * p.Bz;

    float acc[2][NTN][4];
#pragma unroll
    for (int i = 0; i < 2; ++i)
#pragma unroll
        for (int j = 0; j < NTN; ++j)
#pragma unroll
            for (int c = 0; c < 4; ++c) acc[i][j][c] = 0.f;

    float4 ra[2], rb[2];

    // ---- global loads into registers ----
    auto ldA = [&](int k0) {
#pragma unroll
        for (int i = 0; i < 2; ++i) {
            int idx = t + i * 256;
            int r = idx >> 2, c4 = (idx & 3) * 4;
            ra[i] = *(const float4*)(A + (long long)(m0 + r) * p.K + k0 + c4);
        }
    };
    auto ldB = [&](int k0) {
        if (BNT) {
#pragma unroll
            for (int i = 0; i < NLB; ++i) {
                int idx = t + i * 256;
                int r = idx >> 2, c4 = (idx & 3) * 4;
                rb[i] = *(const float4*)(B + (long long)(n0 + r) * p.K + k0 + c4);
            }
        } else {
            int kr = t >> 4, c = (t & 15) * 4;
            rb[0] = *(const float4*)(B + (long long)(k0 + kr) * p.N + n0 + c);
        }
    };
    // ---- register -> smem (with tf32 conversion) ----
    auto stA = [&]() {
#pragma unroll
        for (int i = 0; i < 2; ++i) {
            int idx = t + i * 256;
            int r = idx >> 2, c4 = (idx & 3) * 4;
            As[c4 + 0][r] = f2tf(ra[i].x); As[c4 + 1][r] = f2tf(ra[i].y);
            As[c4 + 2][r] = f2tf(ra[i].z); As[c4 + 3][r] = f2tf(ra[i].w);
        }
    };
    auto stB = [&]() {
        if (BNT) {
#pragma unroll
            for (int i = 0; i < NLB; ++i) {
                int idx = t + i * 256;
                int r = idx >> 2, c4 = (idx & 3) * 4;
                Bs[c4 + 0][r] = f2tf(rb[i].x); Bs[c4 + 1][r] = f2tf(rb[i].y);
                Bs[c4 + 2][r] = f2tf(rb[i].z); Bs[c4 + 3][r] = f2tf(rb[i].w);
            }
        } else {
            int kr = t >> 4, c = (t & 15) * 4;
            Bs[kr][c + 0] = f2tf(rb[0].x); Bs[kr][c + 1] = f2tf(rb[0].y);
            Bs[kr][c + 2] = f2tf(rb[0].z); Bs[kr][c + 3] = f2tf(rb[0].w);
        }
    };
    auto compute = [&]() {
#pragma unroll
        for (int ks = 0; ks < 2; ++ks) {
            const int kr = ks * 8 + (lane & 3);
            unsigned a[2][4];
#pragma unroll
            for (int mt = 0; mt < 2; ++mt) {
                int mr = wm * 32 + mt * 16 + (lane >> 2);
                a[mt][0] = As[kr][mr];     a[mt][1] = As[kr][mr + 8];
                a[mt][2] = As[kr + 4][mr]; a[mt][3] = As[kr + 4][mr + 8];
            }
#pragma unroll
            for (int nt = 0; nt < NTN; ++nt) {
                int nc = wn * WN + nt * 8 + (lane >> 2);
                unsigned b0 = Bs[kr][nc];
                unsigned b1 = Bs[kr + 4][nc];
#pragma unroll
                for (int mt = 0; mt < 2; ++mt) mma8(acc[mt][nt], a[mt], b0, b1);
            }
        }
    };

    const int ntile = p.K >> 4;
    ldA(0); ldB(0);
    stA(); stB();
    __syncthreads();
    for (int it = 0; it < ntile; ++it) {
        if (it + 1 < ntile) { ldA((it + 1) << 4); ldB((it + 1) << 4); }
        compute();
        __syncthreads();
        if (it + 1 < ntile) {
            stA(); stB();
            __syncthreads();
        }
    }

    // ---- epilogue ----
#pragma unroll
    for (int mt = 0; mt < 2; ++mt) {
#pragma unroll
        for (int nt = 0; nt < NTN; ++nt) {
#pragma unroll
            for (int c = 0; c < 4; ++c) {
                int m = m0 + wm * 32 + mt * 16 + (lane >> 2) + ((c >= 2) ? 8 : 0);
                int n = n0 + wn * WN + nt * 8 + 2 * (lane & 3) + (c & 1);
                float v = acc[mt][nt][c];
                if (MODE == M_PLAIN) {
                    p.C[(long long)m * p.N + n] = v + p.bias[n];
                } else if (MODE == M_QKV) {
                    float o = v + p.bias[n];
                    int b = m >> 10, s = m & (SQ - 1);
                    int h = n >> 6, dk = n & 63;
                    p.C[(((long long)(b * NH + h)) * SQ + s) * DKH + dk] = o;
                } else if (MODE == M_RESID) {
                    long long idx = (long long)m * p.N + n;
                    p.C[idx] = p.resid[idx] + v + p.bias[n];
                } else if (MODE == M_RELU) {
                    float o = v + p.bias[n];
                    p.C[(long long)m * p.N + n] = o > 0.f ? o : 0.f;
                } else if (MODE == M_SCORES) {
                    int b = z >> 3;
                    int mk = p.mask[((long long)b * SQ + m) * SQ + n];
                    float o = v * p.scale + p.rbias[z * SQ + n];
                    p.C[(long long)z * p.Cz + (long long)m * SQ + n] = mk ? o : -1e9f;
                } else if (MODE == M_PV) {
                    int b = z >> 3, h = z & 7;
                    p.C[((long long)(b * SQ + m)) * DIM + h * DKH + n] = v;
                }
            }
        }
    }
}

// ---------------- embedding + sinusoidal PE ----------------
__global__ void embed_k(const int* inp, const float* emb, float* x) {
    int row = blockIdx.x;           // b*SQ + s
    int s   = row & (SQ - 1);
    int tok = inp[row];
    const float* e = emb + (long long)tok * DIM;
    const float ln10k_over_d = 9.210340371976184f / (float)DIM;
    for (int d = threadIdx.x; d < DIM; d += 256) {
        int   i2  = d & ~1;
        float dv  = expf(-(float)i2 * ln10k_over_d);
        float arg = (float)s * dv;
        float pe  = (d & 1) ? cosf(arg) : sinf(arg);
        x[(long long)row * DIM + d] = e[d] * 22.62741699796952f + pe;
    }
}

// ---------------- layernorm (ddof=1, /(std+eps)) ----------------
__global__ void ln_k(const float* x, const float* ga, const float* be, float* y) {
    int row = blockIdx.x;
    const float* xr = x + (long long)row * DIM;
    float* yr = y + (long long)row * DIM;
    __shared__ float red[256];
    int t = threadIdx.x;
    float v0 = xr[t], v1 = xr[t + 256];
    red[t] = v0 + v1;
    __syncthreads();
    for (int o = 128; o > 0; o >>= 1) { if (t < o) red[t] += red[t + o]; __syncthreads(); }
    float mean = red[0] * (1.f / (float)DIM);
    __syncthreads();
    float d0 = v0 - mean, d1 = v1 - mean;
    red[t] = d0 * d0 + d1 * d1;
    __syncthreads();
    for (int o = 128; o > 0; o >>= 1) { if (t < o) red[t] += red[t + o]; __syncthreads(); }
    float stdv = sqrtf(red[0] / (float)(DIM - 1));
    float inv  = 1.f / (stdv + 1e-6f);
    yr[t]       = ga[t] * d0 * inv + be[t];
    yr[t + 256] = ga[t + 256] * d1 * inv + be[t + 256];
}

// ---------------- relative bias: r[b,h,k] = scale * dot(q[b,h,k], pe[h,k]) ----
__global__ void relbias_k(const float* q, const float* rel, float* r) {
    int idx  = blockIdx.x * 8 + (threadIdx.x >> 5);   // (b*NH+h)*SQ + k
    int lane = threadIdx.x & 31;
    int k = idx & (SQ - 1);
    int h = (idx >> 10) & (NH - 1);
    const float* qp = q   + (long long)idx * DKH;
    const float* pp = rel + ((long long)h * MAXS + k) * DKH;
    float d = qp[lane] * pp[lane] + qp[lane + 32] * pp[lane + 32];
    for (int o = 16; o > 0; o >>= 1) d += __shfl_xor_sync(0xffffffffu, d, o);
    if (lane == 0) r[idx] = d * 0.125f;
}

// ---------------- row softmax over S=1024 (in place) ----------------
__global__ void softmax_k(float* sc) {
    float* s = sc + (long long)blockIdx.x * SQ;
    __shared__ float red[256];
    int t = threadIdx.x;
    float mx = -1e30f;
    for (int k = t; k < SQ; k += 256) mx = fmaxf(mx, s[k]);
    red[t] = mx; __syncthreads();
    for (int o = 128; o > 0; o >>= 1) { if (t < o) red[t] = fmaxf(red[t], red[t + o]); __syncthreads(); }
    mx = red[0]; __syncthreads();
    float sum = 0.f;
    for (int k = t; k < SQ; k += 256) { float e = expf(s[k] - mx); s[k] = e; sum += e; }
    red[t] = sum; __syncthreads();
    for (int o = 128; o > 0; o >>= 1) { if (t < o) red[t] += red[t + o]; __syncthreads(); }
    float inv = 1.f / red[0];
    __syncthreads();
    for (int k = t; k < SQ; k += 256) s[k] *= inv;
}

// ---------------- log_softmax over vocab (in place on d_out) ----------------
__global__ void logsoftmax_k(float* out) {
    float* r = out + (long long)blockIdx.x * NV;
    __shared__ float red[256];
    int t = threadIdx.x;
    float mx = -1e30f;
    for (int k = t; k < NV; k += 256) mx = fmaxf(mx, r[k]);
    red[t] = mx; __syncthreads();
    for (int o = 128; o > 0; o >>= 1) { if (t < o) red[t] = fmaxf(red[t], red[t + o]); __syncthreads(); }
    mx = red[0]; __syncthreads();
    float sum = 0.f;
    for (int k = t; k < NV; k += 256) sum += expf(r[k] - mx);
    red[t] = sum; __syncthreads();
    for (int o = 128; o > 0; o >>= 1) { if (t < o) red[t] += red[t + o]; __syncthreads(); }
    float lse = mx + logf(red[0]);
    __syncthreads();
    for (int k = t; k < NV; k += 256) r[k] -= lse;
}

// ---------------- host driver ----------------
static inline GP mkgp(const float* A, const float* B, const float* bias, float* C,
                      int M, int N, int K) {
    GP p; p.A = A; p.B = B; p.bias = bias; p.C = C;
    p.resid = nullptr; p.rbias = nullptr; p.mask = nullptr;
    p.M = M; p.N = N; p.K = K; p.Az = 0; p.Bz = 0; p.Cz = 0; p.scale = 1.f;
    return p;
}

extern "C" void kernel_launch(void* const* d_in, const int* in_sizes, int n_in,
                              void* d_out, int out_size) {
    const int*   inp   = (const int*)  d_in[0];
    const int*   mask  = (const int*)  d_in[1];
    const float* emb   = (const float*)d_in[2];
    const float* Wq    = (const float*)d_in[3];
    const float* bq    = (const float*)d_in[4];
    const float* Wk    = (const float*)d_in[5];
    const float* bk    = (const float*)d_in[6];
    const float* Wv    = (const float*)d_in[7];
    const float* bv    = (const float*)d_in[8];
    const float* Wo    = (const float*)d_in[9];
    const float* bo    = (const float*)d_in[10];
    const float* rel   = (const float*)d_in[11];
    const float* ln1a  = (const float*)d_in[12];
    const float* ln1b  = (const float*)d_in[13];
    const float* ln2a  = (const float*)d_in[14];
    const float* ln2b  = (const float*)d_in[15];
    const float* W1    = (const float*)d_in[16];
    const float* b1    = (const float*)d_in[17];
    const float* W2    = (const float*)d_in[18];
    const float* b2    = (const float*)d_in[19];
    const float* lnfa  = (const float*)d_in[20];
    const float* lnfb  = (const float*)d_in[21];
    const float* Wg    = (const float*)d_in[22];
    const float* bg    = (const float*)d_in[23];
    float* out = (float*)d_out;

    float *x, *h, *q, *k_, *v, *rb, *sc, *at, *ff;
    cudaGetSymbolAddress((void**)&x,  g_x);
    cudaGetSymbolAddress((void**)&h,  g_h);
    cudaGetSymbolAddress((void**)&q,  g_q);
    cudaGetSymbolAddress((void**)&k_, g_k);
    cudaGetSymbolAddress((void**)&v,  g_v);
    cudaGetSymbolAddress((void**)&rb, g_rb);
    cudaGetSymbolAddress((void**)&sc, g_sc);
    cudaGetSymbolAddress((void**)&at, g_at);
    cudaGetSymbolAddress((void**)&ff, g_ff);

    const int Mtok = BB * SQ;   // 2048

    embed_k<<<Mtok, 256>>>(inp, emb, x);

    for (int l = 0; l < NL; ++l) {
        const long long wOff = (long long)l * DIM * DIM;

        ln_k<<<Mtok, 256>>>(x, ln1a + l * DIM, ln1b + l * DIM, h);

        // QKV projections, scattered to [B,H,S,DK]
        {
            dim3 g(DIM / 128, Mtok / 128, 1);
            GP pq = mkgp(h, Wq + wOff, bq + l * DIM, q,  Mtok, DIM, DIM);
            GP pk = mkgp(h, Wk + wOff, bk + l * DIM, k_, Mtok, DIM, DIM);
            GP pv = mkgp(h, Wv + wOff, bv + l * DIM, v,  Mtok, DIM, DIM);
            mma_k<M_QKV, true, 128><<<g, 256>>>(pq);
            mma_k<M_QKV, true, 128><<<g, 256>>>(pk);
            mma_k<M_QKV, true, 128><<<g, 256>>>(pv);
        }

        relbias_k<<<BB * NH * SQ / 8, 256>>>(q, rel + (long long)l * NH * MAXS * DKH, rb);

        // scores = scale*(q·k) + r[k], masked
        {
            GP p = mkgp(q, k_, nullptr, sc, SQ, SQ, DKH);
            p.Az = (long long)SQ * DKH; p.Bz = (long long)SQ * DKH;
            p.Cz = (long long)SQ * SQ;
            p.rbias = rb; p.mask = mask; p.scale = 0.125f;
            dim3 g(SQ / 128, SQ / 128, BB * NH);
            mma_k<M_SCORES, true, 128><<<g, 256>>>(p);
        }

        softmax_k<<<BB * NH * SQ, 256>>>(sc);

        // attn = P @ V, scattered back to [B,S,D]
        {
            GP p = mkgp(sc, v, nullptr, at, SQ, DKH, SQ);
            p.Az = (long long)SQ * SQ; p.Bz = (long long)SQ * DKH;
            dim3 g(1, SQ / 128, BB * NH);
            mma_k<M_PV, false, 64><<<g, 256>>>(p);
        }

        // x = x + attn @ Wo^T + bo
        {
            GP p = mkgp(at, Wo + wOff, bo + l * DIM, x, Mtok, DIM, DIM);
            p.resid = x;
            dim3 g(DIM / 128, Mtok / 128, 1);
            mma_k<M_RESID, true, 128><<<g, 256>>>(p);
        }

        ln_k<<<Mtok, 256>>>(x, ln2a + l * DIM, ln2b + l * DIM, h);

        // ffn = relu(h @ W1^T + b1)
        {
            GP p = mkgp(h, W1 + (long long)l * DFF * DIM, b1 + l * DFF, ff, Mtok, DFF, DIM);
            dim3 g(DFF / 128, Mtok / 128, 1);
            mma_k<M_RELU, true, 128><<<g, 256>>>(p);
        }
        // x = x + ffn @ W2^T + b2
        {
            GP p = mkgp(ff, W2 + (long long)l * DIM * DFF, b2 + l * DIM, x, Mtok, DIM, DFF);
            p.resid = x;
            dim3 g(DIM / 128, Mtok / 128, 1);
            mma_k<M_RESID, true, 128><<<g, 256>>>(p);
        }
    }

    ln_k<<<Mtok, 256>>>(x, lnfa, lnfb, h);

    // logits = h @ Wg^T + bg  ->  d_out
    {
        GP p = mkgp(h, Wg, bg, out, Mtok, NV, DIM);
        dim3 g(NV / 128, Mtok / 128, 1);
        mma_k<M_PLAIN, true, 128><<<g, 256>>>(p);
    }

    logsoftmax_k<<<Mtok, 256>>>(out);
}

// round 3
// speedup vs baseline: 1.4270x; 1.0007x over previous
#include <cuda_runtime.h>
#include <math.h>

// Problem constants
#define BB   2
#define SQ   1024
#define DIM  512
#define NH   8
#define DKH  64
#define NL   6
#define DFF  2048
#define NV   32000
#define MAXS 1025   // MAXSEQ+1

// ---------------- device scratch (no allocations allowed) ----------------
__device__ float g_x  [BB*SQ*DIM];
__device__ float g_h  [BB*SQ*DIM];
__device__ float g_qkv[3*BB*SQ*DIM];
__device__ float g_rb [BB*NH*SQ];
__device__ float g_sc [(long long)BB*NH*SQ*SQ];   // 67 MB
__device__ float g_at [BB*SQ*DIM];
__device__ float g_ff [BB*SQ*DFF];

struct GP {
    const float* A; const float* B; const float* B1; const float* B2;
    const float* bias; const float* bias1; const float* bias2;
    const float* resid; const float* rbias; const int* mask;
    float* C;
    int M, N, K;
    long long Az, Bz, Cz;
    float scale;
};

enum { M_PLAIN = 0, M_QKV, M_RESID, M_RELU, M_SCORES, M_PV };

__device__ __forceinline__ unsigned f2tf(float f) {
    unsigned r;
    asm("cvt.rna.tf32.f32 %0, %1;" : "=r"(r) : "f"(f));
    return r;
}

__device__ __forceinline__ void mma8(float* c, const unsigned* a, unsigned b0, unsigned b1) {
    asm volatile(
        "mma.sync.aligned.m16n8k8.row.col.f32.tf32.tf32.f32 "
        "{%0,%1,%2,%3},{%4,%5,%6,%7},{%8,%9},{%0,%1,%2,%3};"
        : "+f"(c[0]), "+f"(c[1]), "+f"(c[2]), "+f"(c[3])
        : "r"(a[0]), "r"(a[1]), "r"(a[2]), "r"(a[3]), "r"(b0), "r"(b1));
}

// ============ TF32 tensor-core GEMM, fragment-order smem, 2-stage ============
// BM=128, BK=32. BN in {64,128}. 256 threads = 8 warps as 4(m) x 2(n).
// Smem tiles are stored in mma-fragment order so fragment fetch = LDS.128.
// BNT=true:  C[m,n] = sum_k A[m,k] * B[n,k]
// BNT=false: C[m,n] = sum_k A[m,k] * B[k,n]   (BN must be 64)
template<int MODE, bool BNT, int BN>
__global__ __launch_bounds__(256) void mma_k(GP p) {
    constexpr int WN    = BN / 2;        // per-warp n extent
    constexpr int NTN   = WN / 8;        // n8 sub-tiles per warp
    constexpr int NPAIR = NTN / 2;       // n16 pairs per warp
    constexpr int ASZ   = 8 * 4 * 128;   // 4096 u32
    constexpr int BSZ   = (BN / 16) * 4 * 128;
    constexpr int NLB   = (BN == 128) ? 4 : 2;

    extern __shared__ unsigned smu[];
    unsigned* Abuf[2] = { smu, smu + ASZ };
    unsigned* Bbuf[2] = { smu + 2 * ASZ, smu + 2 * ASZ + BSZ };

    const int t    = threadIdx.x;
    const int lane = t & 31;
    const int warp = t >> 5;
    const int wm   = warp >> 1;
    const int wn   = warp & 1;
    const int n0   = blockIdx.x * BN;
    const int m0   = blockIdx.y * 128;
    const int z    = blockIdx.z;

    const float* A = p.A + (long long)z * p.Az;
    const float* B;
    const float* bias;
    if (MODE == M_QKV) {
        B    = (z == 0) ? p.B : (z == 1 ? p.B1 : p.B2);
        bias = (z == 0) ? p.bias : (z == 1 ? p.bias1 : p.bias2);
    } else {
        B    = p.B + (long long)z * p.Bz;
        bias = p.bias;
    }

    // fully-masked causal score blocks: write -1e9, skip GEMM
    if (MODE == M_SCORES && n0 >= m0 + 128) {
        float4 neg = make_float4(-1e9f, -1e9f, -1e9f, -1e9f);
        float* Cb = p.C + (long long)z * p.Cz;
#pragma unroll
        for (int i = t; i < 128 * 32; i += 256) {
            int r = i >> 5, c4 = (i & 31) * 4;
            *(float4*)(Cb + (long long)(m0 + r) * SQ + n0 + c4) = neg;
        }
        return;
    }

    float acc[2][NTN][4];
#pragma unroll
    for (int i = 0; i < 2; ++i)
#pragma unroll
        for (int j = 0; j < NTN; ++j)
#pragma unroll
            for (int c = 0; c < 4; ++c) acc[i][j][c] = 0.f;

    float4 ra[4], rb[4];

    auto ldAB = [&](int k0) {
#pragma unroll
        for (int i = 0; i < 4; ++i) {
            int idx = t + i * 256;
            int r = idx >> 3, kq = idx & 7;
            ra[i] = *(const float4*)(A + (long long)(m0 + r) * p.K + k0 + kq * 4);
        }
        if (BNT) {
#pragma unroll
            for (int i = 0; i < NLB; ++i) {
                int idx = t + i * 256;
                int r = idx >> 3, kq = idx & 7;
                rb[i] = *(const float4*)(B + (long long)(n0 + r) * p.K + k0 + kq * 4);
            }
        } else {
#pragma unroll
            for (int i = 0; i < 2; ++i) {
                int idx = t + i * 256;
                int kr = idx >> 4, nq = idx & 15;
                rb[i] = *(const float4*)(B + (long long)(k0 + kr) * p.N + n0 + nq * 4);
            }
        }
    };

    auto stAB = [&](unsigned* Ad, unsigned* Bd) {
#pragma unroll
        for (int i = 0; i < 4; ++i) {
            int idx = t + i * 256;
            int r = idx >> 3, kq = idx & 7;
            int base = (kq >> 1) * 8 * 128 + (r >> 4) * 128
                     + (r & 7) * 16 + ((r >> 3) & 1) + 2 * (kq & 1);
            float* v = (float*)&ra[i];
#pragma unroll
            for (int j = 0; j < 4; ++j) Ad[base + j * 4] = f2tf(v[j]);
        }
        if (BNT) {
#pragma unroll
            for (int i = 0; i < NLB; ++i) {
                int idx = t + i * 256;
                int r = idx >> 3, kq = idx & 7;
                int nb = r >> 3;
                int base = ((kq >> 1) * (BN / 16) + (nb >> 1)) * 128
                         + (r & 7) * 16 + (nb & 1) * 2 + (kq & 1);
                float* v = (float*)&rb[i];
#pragma unroll
                for (int j = 0; j < 4; ++j) Bd[base + j * 4] = f2tf(v[j]);
            }
        } else {
#pragma unroll
            for (int i = 0; i < 2; ++i) {
                int idx = t + i * 256;
                int kr = idx >> 4, nq = idx & 15;
                int nb = nq >> 1;
                int base = ((kr >> 3) * (BN / 16) + (nb >> 1)) * 128
                         + (nq & 1) * 64 + (kr & 3) * 4 + (nb & 1) * 2 + ((kr >> 2) & 1);
                float* v = (float*)&rb[i];
#pragma unroll
                for (int j = 0; j < 4; ++j) Bd[base + j * 16] = f2tf(v[j]);
            }
        }
    };

    auto compute = [&](const unsigned* Ab, const unsigned* Bb) {
#pragma unroll
        for (int ks = 0; ks < 4; ++ks) {
            uint4 av[2];
#pragma unroll
            for (int mt = 0; mt < 2; ++mt)
                av[mt] = *(const uint4*)(Ab + (ks * 8 + wm * 2 + mt) * 128 + lane * 4);
#pragma unroll
            for (int pp = 0; pp < NPAIR; ++pp) {
                uint4 bv = *(const uint4*)(Bb + (ks * (BN / 16) + wn * NPAIR + pp) * 128 + lane * 4);
#pragma unroll
                for (int mt = 0; mt < 2; ++mt) {
                    mma8(acc[mt][2 * pp + 0], (const unsigned*)&av[mt], bv.x, bv.y);
                    mma8(acc[mt][2 * pp + 1], (const unsigned*)&av[mt], bv.z, bv.w);
                }
            }
        }
    };

    int ntile = p.K >> 5;
    if (MODE == M_PV) {  // causal: P[m][k]==0 for k>m, skip those K tiles
        int lim = (m0 + 128) >> 5;
        if (lim < ntile) ntile = lim;
    }

    ldAB(0);
    stAB(Abuf[0], Bbuf[0]);
    __syncthreads();
    for (int it = 0; it < ntile; ++it) {
        if (it + 1 < ntile) ldAB((it + 1) << 5);
        compute(Abuf[it & 1], Bbuf[it & 1]);
        if (it + 1 < ntile) stAB(Abuf[(it + 1) & 1], Bbuf[(it + 1) & 1]);
        __syncthreads();
    }

    // ---- epilogue ----
#pragma unroll
    for (int mt = 0; mt < 2; ++mt) {
#pragma unroll
        for (int nt = 0; nt < NTN; ++nt) {
#pragma unroll
            for (int c = 0; c < 4; ++c) {
                int m = m0 + wm * 32 + mt * 16 + (lane >> 2) + ((c >= 2) ? 8 : 0);
                int n = n0 + wn * WN + nt * 8 + 2 * (lane & 3) + (c & 1);
                float v = acc[mt][nt][c];
                if (MODE == M_PLAIN) {
                    p.C[(long long)m * p.N + n] = v + bias[n];
                } else if (MODE == M_QKV) {
                    float o = v + bias[n];
                    int b = m >> 10, s = m & (SQ - 1);
                    int h = n >> 6, dk = n & 63;
                    p.C[(long long)z * p.Cz + (((long long)(b * NH + h)) * SQ + s) * DKH + dk] = o;
                } else if (MODE == M_RESID) {
                    long long idx = (long long)m * p.N + n;
                    p.C[idx] = p.resid[idx] + v + bias[n];
                } else if (MODE == M_RELU) {
                    float o = v + bias[n];
                    p.C[(long long)m * p.N + n] = o > 0.f ? o : 0.f;
                } else if (MODE == M_SCORES) {
                    int b = z >> 3;
                    int mk = p.mask[((long long)b * SQ + m) * SQ + n];
                    float o = v * p.scale + p.rbias[z * SQ + n];
                    p.C[(long long)z * p.Cz + (long long)m * SQ + n] = mk ? o : -1e9f;
                } else if (MODE == M_PV) {
                    int b = z >> 3, h = z & 7;
                    p.C[((long long)(b * SQ + m)) * DIM + h * DKH + n] = v;
                }
            }
        }
    }
}

// ---------------- embedding + sinusoidal PE ----------------
__global__ void embed_k(const int* inp, const float* emb, float* x) {
    int row = blockIdx.x;
    int s   = row & (SQ - 1);
    int tok = inp[row];
    const float* e = emb + (long long)tok * DIM;
    const float ln10k_over_d = 9.210340371976184f / (float)DIM;
    for (int d = threadIdx.x; d < DIM; d += 256) {
        int   i2  = d & ~1;
        float dv  = expf(-(float)i2 * ln10k_over_d);
        float arg = (float)s * dv;
        float pe  = (d & 1) ? cosf(arg) : sinf(arg);
        x[(long long)row * DIM + d] = e[d] * 22.62741699796952f + pe;
    }
}

// ---------------- layernorm (ddof=1, /(std+eps)) ----------------
__global__ void ln_k(const float* x, const float* ga, const float* be, float* y) {
    int row = blockIdx.x;
    const float* xr = x + (long long)row * DIM;
    float* yr = y + (long long)row * DIM;
    __shared__ float red[256];
    int t = threadIdx.x;
    float v0 = xr[t], v1 = xr[t + 256];
    red[t] = v0 + v1;
    __syncthreads();
    for (int o = 128; o > 0; o >>= 1) { if (t < o) red[t] += red[t + o]; __syncthreads(); }
    float mean = red[0] * (1.f / (float)DIM);
    __syncthreads();
    float d0 = v0 - mean, d1 = v1 - mean;
    red[t] = d0 * d0 + d1 * d1;
    __syncthreads();
    for (int o = 128; o > 0; o >>= 1) { if (t < o) red[t] += red[t + o]; __syncthreads(); }
    float stdv = sqrtf(red[0] / (float)(DIM - 1));
    float inv  = 1.f / (stdv + 1e-6f);
    yr[t]       = ga[t] * d0 * inv + be[t];
    yr[t + 256] = ga[t + 256] * d1 * inv + be[t + 256];
}

// ---------------- relative bias: r[b,h,k] = scale * dot(q[b,h,k], pe[h,k]) ----
__global__ void relbias_k(const float* q, const float* rel, float* r) {
    int idx  = blockIdx.x * 8 + (threadIdx.x >> 5);
    int lane = threadIdx.x & 31;
    int k = idx & (SQ - 1);
    int h = (idx >> 10) & (NH - 1);
    const float* qp = q   + (long long)idx * DKH;
    const float* pp = rel + ((long long)h * MAXS + k) * DKH;
    float d = qp[lane] * pp[lane] + qp[lane + 32] * pp[lane + 32];
    for (int o = 16; o > 0; o >>= 1) d += __shfl_xor_sync(0xffffffffu, d, o);
    if (lane == 0) r[idx] = d * 0.125f;
}

// ---------------- row softmax over S=1024 (in place) ----------------
__global__ void softmax_k(float* sc) {
    float* s = sc + (long long)blockIdx.x * SQ;
    __shared__ float red[256];
    int t = threadIdx.x;
    float mx = -1e30f;
    for (int k = t; k < SQ; k += 256) mx = fmaxf(mx, s[k]);
    red[t] = mx; __syncthreads();
    for (int o = 128; o > 0; o >>= 1) { if (t < o) red[t] = fmaxf(red[t], red[t + o]); __syncthreads(); }
    mx = red[0]; __syncthreads();
    float sum = 0.f;
    for (int k = t; k < SQ; k += 256) { float e = expf(s[k] - mx); s[k] = e; sum += e; }
    red[t] = sum; __syncthreads();
    for (int o = 128; o > 0; o >>= 1) { if (t < o) red[t] += red[t + o]; __syncthreads(); }
    float inv = 1.f / red[0];
    __syncthreads();
    for (int k = t; k < SQ; k += 256) s[k] *= inv;
}

// ---------------- log_softmax over vocab (in place on d_out) ----------------
__global__ void logsoftmax_k(float* out) {
    float* r = out + (long long)blockIdx.x * NV;
    __shared__ float red[256];
    int t = threadIdx.x;
    float mx = -1e30f;
    for (int k = t; k < NV; k += 256) mx = fmaxf(mx, r[k]);
    red[t] = mx; __syncthreads();
    for (int o = 128; o > 0; o >>= 1) { if (t < o) red[t] = fmaxf(red[t], red[t + o]); __syncthreads(); }
    mx = red[0]; __syncthreads();
    float sum = 0.f;
    for (int k = t; k < NV; k += 256) sum += expf(r[k] - mx);
    red[t] = sum; __syncthreads();
    for (int o = 128; o > 0; o >>= 1) { if (t < o) red[t] += red[t + o]; __syncthreads(); }
    float lse = mx + logf(red[0]);
    __syncthreads();
    for (int k = t; k < NV; k += 256) r[k] -= lse;
}

// ---------------- host driver ----------------
static inline GP mkgp(const float* A, const float* B, const float* bias, float* C,
                      int M, int N, int K) {
    GP p; p.A = A; p.B = B; p.bias = bias; p.C = C;
    p.B1 = nullptr; p.B2 = nullptr; p.bias1 = nullptr; p.bias2 = nullptr;
    p.resid = nullptr; p.rbias = nullptr; p.mask = nullptr;
    p.M = M; p.N = N; p.K = K; p.Az = 0; p.Bz = 0; p.Cz = 0; p.scale = 1.f;
    return p;
}

#define SMEM128 65536
#define SMEM64  49152

extern "C" void kernel_launch(void* const* d_in, const int* in_sizes, int n_in,
                              void* d_out, int out_size) {
    const int*   inp   = (const int*)  d_in[0];
    const int*   mask  = (const int*)  d_in[1];
    const float* emb   = (const float*)d_in[2];
    const float* Wq    = (const float*)d_in[3];
    const float* bq    = (const float*)d_in[4];
    const float* Wk    = (const float*)d_in[5];
    const float* bk    = (const float*)d_in[6];
    const float* Wv    = (const float*)d_in[7];
    const float* bv    = (const float*)d_in[8];
    const float* Wo    = (const float*)d_in[9];
    const float* bo    = (const float*)d_in[10];
    const float* rel   = (const float*)d_in[11];
    const float* ln1a  = (const float*)d_in[12];
    const float* ln1b  = (const float*)d_in[13];
    const float* ln2a  = (const float*)d_in[14];
    const float* ln2b  = (const float*)d_in[15];
    const float* W1    = (const float*)d_in[16];
    const float* b1    = (const float*)d_in[17];
    const float* W2    = (const float*)d_in[18];
    const float* b2    = (const float*)d_in[19];
    const float* lnfa  = (const float*)d_in[20];
    const float* lnfb  = (const float*)d_in[21];
    const float* Wg    = (const float*)d_in[22];
    const float* bg    = (const float*)d_in[23];
    float* out = (float*)d_out;

    float *x, *h, *qkv, *rb, *sc, *at, *ff;
    cudaGetSymbolAddress((void**)&x,   g_x);
    cudaGetSymbolAddress((void**)&h,   g_h);
    cudaGetSymbolAddress((void**)&qkv, g_qkv);
    cudaGetSymbolAddress((void**)&rb,  g_rb);
    cudaGetSymbolAddress((void**)&sc,  g_sc);
    cudaGetSymbolAddress((void**)&at,  g_at);
    cudaGetSymbolAddress((void**)&ff,  g_ff);

    const int Mtok = BB * SQ;                  // 2048
    const long long TSZ = (long long)Mtok * DIM;
    float* q  = qkv;
    float* k_ = qkv + TSZ;
    float* v  = qkv + 2 * TSZ;

    cudaFuncSetAttribute(mma_k<M_QKV,    true,  128>, cudaFuncAttributeMaxDynamicSharedMemorySize, SMEM128);
    cudaFuncSetAttribute(mma_k<M_SCORES, true,  128>, cudaFuncAttributeMaxDynamicSharedMemorySize, SMEM128);
    cudaFuncSetAttribute(mma_k<M_RELU,   true,  128>, cudaFuncAttributeMaxDynamicSharedMemorySize, SMEM128);
    cudaFuncSetAttribute(mma_k<M_PLAIN,  true,  128>, cudaFuncAttributeMaxDynamicSharedMemorySize, SMEM128);
    cudaFuncSetAttribute(mma_k<M_RESID,  true,  64 >, cudaFuncAttributeMaxDynamicSharedMemorySize, SMEM64);
    cudaFuncSetAttribute(mma_k<M_PV,     false, 64 >, cudaFuncAttributeMaxDynamicSharedMemorySize, SMEM64);

    embed_k<<<Mtok, 256>>>(inp, emb, x);

    for (int l = 0; l < NL; ++l) {
        const long long wOff = (long long)l * DIM * DIM;

        ln_k<<<Mtok, 256>>>(x, ln1a + l * DIM, ln1b + l * DIM, h);

        // fused QKV: z picks W/bias/output slot
        {
            GP p = mkgp(h, Wq + wOff, bq + l * DIM, qkv, Mtok, DIM, DIM);
            p.B1 = Wk + wOff;  p.B2 = Wv + wOff;
            p.bias1 = bk + l * DIM; p.bias2 = bv + l * DIM;
            p.Cz = TSZ;
            dim3 g(DIM / 128, Mtok / 128, 3);
            mma_k<M_QKV, true, 128><<<g, 256, SMEM128>>>(p);
        }

        relbias_k<<<BB * NH * SQ / 8, 256>>>(q, rel + (long long)l * NH * MAXS * DKH, rb);

        // scores = scale*(q·k) + r[k], masked (causal blocks skip GEMM)
        {
            GP p = mkgp(q, k_, nullptr, sc, SQ, SQ, DKH);
            p.Az = (long long)SQ * DKH; p.Bz = (long long)SQ * DKH;
            p.Cz = (long long)SQ * SQ;
            p.rbias = rb; p.mask = mask; p.scale = 0.125f;
            dim3 g(SQ / 128, SQ / 128, BB * NH);
            mma_k<M_SCORES, true, 128><<<g, 256, SMEM128>>>(p);
        }

        softmax_k<<<BB * NH * SQ, 256>>>(sc);

        // attn = P @ V (causal K-tile skip), scattered back to [B,S,D]
        {
            GP p = mkgp(sc, v, nullptr, at, SQ, DKH, SQ);
            p.Az = (long long)SQ * SQ; p.Bz = (long long)SQ * DKH;
            dim3 g(1, SQ / 128, BB * NH);
            mma_k<M_PV, false, 64><<<g, 256, SMEM64>>>(p);
        }

        // x = x + attn @ Wo^T + bo
        {
            GP p = mkgp(at, Wo + wOff, bo + l * DIM, x, Mtok, DIM, DIM);
            p.resid = x;
            dim3 g(DIM / 64, Mtok / 128, 1);
            mma_k<M_RESID, true, 64><<<g, 256, SMEM64>>>(p);
        }

        ln_k<<<Mtok, 256>>>(x, ln2a + l * DIM, ln2b + l * DIM, h);

        // ffn = relu(h @ W1^T + b1)
        {
            GP p = mkgp(h, W1 + (long long)l * DFF * DIM, b1 + l * DFF, ff, Mtok, DFF, DIM);
            dim3 g(DFF / 128, Mtok / 128, 1);
            mma_k<M_RELU, true, 128><<<g, 256, SMEM128>>>(p);
        }
        // x = x + ffn @ W2^T + b2
        {
            GP p = mkgp(ff, W2 + (long long)l * DIM * DFF, b2 + l * DIM, x, Mtok, DIM, DFF);
            p.resid = x;
            dim3 g(DIM / 64, Mtok / 128, 1);
            mma_k<M_RESID, true, 64><<<g, 256, SMEM64>>>(p);
        }
    }

    ln_k<<<Mtok, 256>>>(x, lnfa, lnfb, h);

    // logits = h @ Wg^T + bg  ->  d_out
    {
        GP p = mkgp(h, Wg, bg, out, Mtok, NV, DIM);
        dim3 g(NV / 128, Mtok / 128, 1);
        mma_k<M_PLAIN, true, 128><<<g, 256, SMEM128>>>(p);
    }

    logsoftmax_k<<<Mtok, 256>>>(out);
}

// round 5
// speedup vs baseline: 3.5283x; 2.4725x over previous
#include <cuda_runtime.h>
#include <cuda_bf16.h>
#include <math.h>

// Problem constants
#define BB   2
#define SQ   1024
#define DIM  512
#define NH   8
#define DKH  64
#define NL   6
#define DFF  2048
#define NV   32000
#define MAXS 1025   // MAXSEQ+1

typedef unsigned int u32;
typedef __nv_bfloat16 bf16;

// ---------------- device scratch (no allocations allowed) ----------------
__device__ float g_x   [BB*SQ*DIM];
__device__ bf16  g_h   [BB*SQ*DIM];
__device__ bf16  g_qkvb[3*BB*SQ*DIM];              // q[B,H,S,DK], k[B,H,S,DK], vT[B,H,DK,S]
__device__ float g_rb  [BB*NH*SQ];
__device__ float g_sc  [(long long)BB*NH*SQ*SQ];   // 67 MB fp32 scores
__device__ bf16  g_pb  [(long long)BB*NH*SQ*SQ];   // 33 MB bf16 probabilities
__device__ bf16  g_at  [BB*SQ*DIM];
__device__ bf16  g_ff  [BB*SQ*DFF];
__device__ bf16  g_wb  [35258368];                 // all weights as bf16

#define OFF_WQ 0
#define OFF_WK 1572864
#define OFF_WV 3145728
#define OFF_WO 4718592
#define OFF_W1 6291456
#define OFF_W2 12582912
#define OFF_WG 18874368

// ======================= PTX helpers =======================
__device__ __forceinline__ u32 sm32(const void* p) {
    u32 a;
    asm("{ .reg .u64 t; cvta.to.shared.u64 t, %1; cvt.u32.u64 %0, t; }" : "=r"(a) : "l"(p));
    return a;
}
__device__ __forceinline__ void cp_async16(u32 s, const void* g) {
    asm volatile("cp.async.cg.shared.global [%0], [%1], 16;" :: "r"(s), "l"(g));
}
#define CP_COMMIT()  asm volatile("cp.async.commit_group;" ::: "memory")
#define CP_WAIT(N)   asm volatile("cp.async.wait_group " #N ";" ::: "memory")

#define LDSM4(r, addr) \
    asm volatile("ldmatrix.sync.aligned.m8n8.x4.shared.b16 {%0,%1,%2,%3}, [%4];" \
        : "=r"((r)[0]), "=r"((r)[1]), "=r"((r)[2]), "=r"((r)[3]) : "r"(addr))

__device__ __forceinline__ void mma16816(float* c, const u32* a, u32 b0, u32 b1) {
    asm volatile(
        "mma.sync.aligned.m16n8k16.row.col.f32.bf16.bf16.f32 "
        "{%0,%1,%2,%3},{%4,%5,%6,%7},{%8,%9},{%0,%1,%2,%3};"
        : "+f"(c[0]), "+f"(c[1]), "+f"(c[2]), "+f"(c[3])
        : "r"(a[0]), "r"(a[1]), "r"(a[2]), "r"(a[3]), "r"(b0), "r"(b1));
}

// ======================= bf16 NT GEMM (ldmatrix + mma.m16n8k16) =======================
// C[m,n] = sum_k A[m,k] * B[n,k]; both bf16, K contiguous.
// BM=128, BK=32 (64B smem rows, XOR-swizzled), BN in {64,128}.
// 256 threads = 8 warps as 4(m) x 2(n). 4-stage cp.async pipeline.
struct GP {
    const bf16* A; const bf16* B; const bf16* B1; const bf16* B2;
    const float* bias; const float* bias1; const float* bias2;
    const float* resid; const float* rbias; const int* mask;
    float* C; bf16* Cb;
    int N, K;
    long long Az, Bz, Cz;
    float scale;
};
enum { M_PLAIN = 0, M_QKV, M_RESID, M_RELU, M_SCORES, M_PV };

template<int MODE, int BN>
__global__ __launch_bounds__(256) void bmma_k(GP p) {
    constexpr int WN     = BN / 2;       // per-warp n extent
    constexpr int NTN    = WN / 8;       // n8 sub-tiles per warp
    constexpr int NB16   = WN / 16;      // n16 ldmatrix groups per warp
    constexpr int ABYTES = 128 * 64;
    constexpr int BBYTES = BN * 64;
    constexpr int STG    = ABYTES + BBYTES;

    extern __shared__ char sm[];
    const u32 sb = sm32(sm);
    const int t = threadIdx.x, lane = t & 31, warp = t >> 5;
    const int wm = warp >> 1, wn = warp & 1;
    const int n0 = blockIdx.x * BN, m0 = blockIdx.y * 128, z = blockIdx.z;

    const bf16* A = p.A + (long long)z * p.Az;
    const bf16* B; const float* bias;
    if (MODE == M_QKV) {
        B    = (z == 0) ? p.B : (z == 1 ? p.B1 : p.B2);
        bias = (z == 0) ? p.bias : (z == 1 ? p.bias1 : p.bias2);
    } else {
        B    = p.B + (long long)z * p.Bz;
        bias = p.bias;
    }

    // fully-masked causal score blocks: constant fill, no GEMM
    if (MODE == M_SCORES && n0 >= m0 + 128) {
        float4 neg = make_float4(-1e9f, -1e9f, -1e9f, -1e9f);
        float* Cb = p.C + (long long)z * p.Cz;
        for (int i = t; i < 128 * (BN / 4); i += 256) {
            int r = i / (BN / 4), c4 = (i % (BN / 4)) * 4;
            *(float4*)(Cb + (long long)(m0 + r) * SQ + n0 + c4) = neg;
        }
        return;
    }

    int ntile = p.K >> 5;
    if (MODE == M_PV) {               // causal: P[m][k]==0 for k>m
        int lim = (m0 + 128) >> 5;
        if (lim < ntile) ntile = lim;
    }

    auto fill = [&](int it) {
        u32 ab = sb + (it & 3) * STG;
        u32 bb = ab + ABYTES;
        int k0 = it << 5;
        const bf16* Ag = A + (long long)m0 * p.K + k0;
        const bf16* Bg = B + (long long)n0 * p.K + k0;
#pragma unroll
        for (int i = 0; i < 2; ++i) {               // A: 128 rows x 4 16B chunks
            int idx = t + i * 256;
            int r = idx >> 2, c = idx & 3;
            cp_async16(ab + r * 64 + ((c ^ ((r >> 1) & 3)) << 4), Ag + (long long)r * p.K + c * 8);
        }
#pragma unroll
        for (int i = 0; i < BN / 64; ++i) {         // B: BN rows x 4 16B chunks
            int idx = t + i * 256;
            int r = idx >> 2, c = idx & 3;
            cp_async16(bb + r * 64 + ((c ^ ((r >> 1) & 3)) << 4), Bg + (long long)r * p.K + c * 8);
        }
        CP_COMMIT();
    };

    float acc[2][NTN][4];
#pragma unroll
    for (int i = 0; i < 2; ++i)
#pragma unroll
        for (int j = 0; j < NTN; ++j)
#pragma unroll
            for (int c = 0; c < 4; ++c) acc[i][j][c] = 0.f;

    for (int s = 0; s < 3 && s < ntile; ++s) fill(s);

    for (int it = 0; it < ntile; ++it) {
        int w = ntile - it - 1; if (w > 2) w = 2;
        if (w == 2) { CP_WAIT(2); } else if (w == 1) { CP_WAIT(1); } else { CP_WAIT(0); }
        __syncthreads();
        if (it + 3 < ntile) fill(it + 3);

        u32 ab = sb + (it & 3) * STG;
        u32 bb = ab + ABYTES;
#pragma unroll
        for (int ks = 0; ks < 2; ++ks) {
            const int cc = ks * 2 + (lane >> 4);
            u32 a[2][4];
#pragma unroll
            for (int mt = 0; mt < 2; ++mt) {
                int mr = wm * 32 + mt * 16 + (lane & 7) + ((lane >> 3) & 1) * 8;
                LDSM4(a[mt], ab + mr * 64 + ((cc ^ ((mr >> 1) & 3)) << 4));
            }
#pragma unroll
            for (int nb = 0; nb < NB16; ++nb) {
                int nr = wn * WN + nb * 16 + (lane & 7) + ((lane >> 3) & 1) * 8;
                u32 b[4];
                LDSM4(b, bb + nr * 64 + ((cc ^ ((nr >> 1) & 3)) << 4));
#pragma unroll
                for (int mt = 0; mt < 2; ++mt) {
                    mma16816(acc[mt][2 * nb + 0], a[mt], b[0], b[2]);
                    mma16816(acc[mt][2 * nb + 1], a[mt], b[1], b[3]);
                }
            }
        }
    }

    // ---- epilogue ----
#pragma unroll
    for (int mt = 0; mt < 2; ++mt) {
#pragma unroll
        for (int nt = 0; nt < NTN; ++nt) {
#pragma unroll
            for (int c = 0; c < 4; ++c) {
                int m = m0 + wm * 32 + mt * 16 + (lane >> 2) + ((c >= 2) ? 8 : 0);
                int n = n0 + wn * WN + nt * 8 + 2 * (lane & 3) + (c & 1);
                float v = acc[mt][nt][c];
                if (MODE == M_PLAIN) {
                    p.C[(long long)m * p.N + n] = v + bias[n];
                } else if (MODE == M_QKV) {
                    float o = v + bias[n];
                    int b = m >> 10, s2 = m & (SQ - 1);
                    int hh = n >> 6, dk = n & 63;
                    long long TSZ = (long long)BB * SQ * DIM;
                    if (z < 2)   // q, k: [B,H,S,DK]
                        p.Cb[z * TSZ + (((long long)(b * NH + hh)) * SQ + s2) * DKH + dk] = __float2bfloat16_rn(o);
                    else         // vT: [B,H,DK,S]
                        p.Cb[2 * TSZ + (((long long)(b * NH + hh)) * DKH + dk) * SQ + s2] = __float2bfloat16_rn(o);
                } else if (MODE == M_RESID) {
                    long long idx = (long long)m * p.N + n;
                    p.C[idx] = p.resid[idx] + v + bias[n];
                } else if (MODE == M_RELU) {
                    float o = v + bias[n];
                    p.Cb[(long long)m * p.N + n] = __float2bfloat16_rn(o > 0.f ? o : 0.f);
                } else if (MODE == M_SCORES) {
                    int b = z >> 3;
                    int mk = p.mask[((long long)b * SQ + m) * SQ + n];
                    float o = v * p.scale + p.rbias[z * SQ + n];
                    p.C[(long long)z * p.Cz + (long long)m * SQ + n] = mk ? o : -1e9f;
                } else if (MODE == M_PV) {
                    int b = z >> 3, hh = z & 7;
                    p.Cb[((long long)(b * SQ + m)) * DIM + hh * DKH + n] = __float2bfloat16_rn(v);
                }
            }
        }
    }
}

// ---------------- weight f32 -> bf16 conversion ----------------
__global__ void cvt_k(const float* s, bf16* d, int n) {
    int i = (blockIdx.x * 256 + threadIdx.x) * 4;
    if (i < n) {
        float4 v = *(const float4*)(s + i);
        d[i + 0] = __float2bfloat16_rn(v.x);
        d[i + 1] = __float2bfloat16_rn(v.y);
        d[i + 2] = __float2bfloat16_rn(v.z);
        d[i + 3] = __float2bfloat16_rn(v.w);
    }
}

// ---------------- embedding + sinusoidal PE ----------------
__global__ void embed_k(const int* inp, const float* emb, float* x) {
    int row = blockIdx.x;
    int s   = row & (SQ - 1);
    int tok = inp[row];
    const float* e = emb + (long long)tok * DIM;
    const float ln10k_over_d = 9.210340371976184f / (float)DIM;
    for (int d = threadIdx.x; d < DIM; d += 256) {
        int   i2  = d & ~1;
        float dv  = expf(-(float)i2 * ln10k_over_d);
        float arg = (float)s * dv;
        float pe  = (d & 1) ? cosf(arg) : sinf(arg);
        x[(long long)row * DIM + d] = e[d] * 22.62741699796952f + pe;
    }
}

// ---------------- layernorm (ddof=1, /(std+eps)), bf16 output ----------------
__global__ void ln_k(const float* x, const float* ga, const float* be, bf16* y) {
    int row = blockIdx.x;
    const float* xr = x + (long long)row * DIM;
    bf16* yr = y + (long long)row * DIM;
    __shared__ float red[256];
    int t = threadIdx.x;
    float v0 = xr[t], v1 = xr[t + 256];
    red[t] = v0 + v1;
    __syncthreads();
    for (int o = 128; o > 0; o >>= 1) { if (t < o) red[t] += red[t + o]; __syncthreads(); }
    float mean = red[0] * (1.f / (float)DIM);
    __syncthreads();
    float d0 = v0 - mean, d1 = v1 - mean;
    red[t] = d0 * d0 + d1 * d1;
    __syncthreads();
    for (int o = 128; o > 0; o >>= 1) { if (t < o) red[t] += red[t + o]; __syncthreads(); }
    float stdv = sqrtf(red[0] / (float)(DIM - 1));
    float inv  = 1.f / (stdv + 1e-6f);
    yr[t]       = __float2bfloat16_rn(ga[t] * d0 * inv + be[t]);
    yr[t + 256] = __float2bfloat16_rn(ga[t + 256] * d1 * inv + be[t + 256]);
}

// ---------------- relative bias: r[b,h,k] = scale * dot(q[b,h,k], pe[h,k]) ----
__global__ void relbias_k(const bf16* q, const float* rel, float* r) {
    int idx  = blockIdx.x * 8 + (threadIdx.x >> 5);
    int lane = threadIdx.x & 31;
    int k = idx & (SQ - 1);
    int h = (idx >> 10) & (NH - 1);
    const bf16*  qp = q   + (long long)idx * DKH;
    const float* pp = rel + ((long long)h * MAXS + k) * DKH;
    float d = __bfloat162float(qp[lane]) * pp[lane]
            + __bfloat162float(qp[lane + 32]) * pp[lane + 32];
    for (int o = 16; o > 0; o >>= 1) d += __shfl_xor_sync(0xffffffffu, d, o);
    if (lane == 0) r[idx] = d * 0.125f;
}

// ---------------- row softmax over S=1024 (fp32 in, bf16 out) ----------------
__global__ void softmax_k(const float* sc, bf16* pb) {
    const float* s = sc + (long long)blockIdx.x * SQ;
    bf16* pd = pb + (long long)blockIdx.x * SQ;
    __shared__ float red[256];
    int t = threadIdx.x;
    float v[4];
#pragma unroll
    for (int i = 0; i < 4; ++i) v[i] = s[t + i * 256];
    float mx = fmaxf(fmaxf(v[0], v[1]), fmaxf(v[2], v[3]));
    red[t] = mx; __syncthreads();
    for (int o = 128; o > 0; o >>= 1) { if (t < o) red[t] = fmaxf(red[t], red[t + o]); __syncthreads(); }
    mx = red[0]; __syncthreads();
    float sum = 0.f;
#pragma unroll
    for (int i = 0; i < 4; ++i) { v[i] = expf(v[i] - mx); sum += v[i]; }
    red[t] = sum; __syncthreads();
    for (int o = 128; o > 0; o >>= 1) { if (t < o) red[t] += red[t + o]; __syncthreads(); }
    float inv = 1.f / red[0];
#pragma unroll
    for (int i = 0; i < 4; ++i) pd[t + i * 256] = __float2bfloat16_rn(v[i] * inv);
}

// ---------------- log_softmax over vocab (in place on d_out) ----------------
__global__ void logsoftmax_k(float* out) {
    float* r = out + (long long)blockIdx.x * NV;
    __shared__ float red[256];
    int t = threadIdx.x;
    float mx = -1e30f;
    for (int k = t; k < NV; k += 256) mx = fmaxf(mx, r[k]);
    red[t] = mx; __syncthreads();
    for (int o = 128; o > 0; o >>= 1) { if (t < o) red[t] = fmaxf(red[t], red[t + o]); __syncthreads(); }
    mx = red[0]; __syncthreads();
    float sum = 0.f;
    for (int k = t; k < NV; k += 256) sum += expf(r[k] - mx);
    red[t] = sum; __syncthreads();
    for (int o = 128; o > 0; o >>= 1) { if (t < o) red[t] += red[t + o]; __syncthreads(); }
    float lse = mx + logf(red[0]);
    __syncthreads();
    for (int k = t; k < NV; k += 256) r[k] -= lse;
}

// ---------------- host driver ----------------
#define SMEM_BN128 65536
#define SMEM_BN64  49152

static inline GP mkgp(const bf16* A, const bf16* B, const float* bias) {
    GP p; p.A = A; p.B = B; p.B1 = nullptr; p.B2 = nullptr;
    p.bias = bias; p.bias1 = nullptr; p.bias2 = nullptr;
    p.resid = nullptr; p.rbias = nullptr; p.mask = nullptr;
    p.C = nullptr; p.Cb = nullptr;
    p.N = 0; p.K = 0; p.Az = 0; p.Bz = 0; p.Cz = 0; p.scale = 1.f;
    return p;
}

extern "C" void kernel_launch(void* const* d_in, const int* in_sizes, int n_in,
                              void* d_out, int out_size) {
    const int*   inp   = (const int*)  d_in[0];
    const int*   mask  = (const int*)  d_in[1];
    const float* emb   = (const float*)d_in[2];
    const float* Wq    = (const float*)d_in[3];
    const float* bq    = (const float*)d_in[4];
    const float* Wk    = (const float*)d_in[5];
    const float* bk    = (const float*)d_in[6];
    const float* Wv    = (const float*)d_in[7];
    const float* bv    = (const float*)d_in[8];
    const float* Wo    = (const float*)d_in[9];
    const float* bo    = (const float*)d_in[10];
    const float* rel   = (const float*)d_in[11];
    const float* ln1a  = (const float*)d_in[12];
    const float* ln1b  = (const float*)d_in[13];
    const float* ln2a  = (const float*)d_in[14];
    const float* ln2b  = (const float*)d_in[15];
    const float* W1    = (const float*)d_in[16];
    const float* b1    = (const float*)d_in[17];
    const float* W2    = (const float*)d_in[18];
    const float* b2    = (const float*)d_in[19];
    const float* lnfa  = (const float*)d_in[20];
    const float* lnfb  = (const float*)d_in[21];
    const float* Wg    = (const float*)d_in[22];
    const float* bg    = (const float*)d_in[23];
    float* out = (float*)d_out;

    float *x, *rb, *sc;
    bf16 *h, *qkvb, *pb, *at, *ff, *wb;
    cudaGetSymbolAddress((void**)&x,    g_x);
    cudaGetSymbolAddress((void**)&h,    g_h);
    cudaGetSymbolAddress((void**)&qkvb, g_qkvb);
    cudaGetSymbolAddress((void**)&rb,   g_rb);
    cudaGetSymbolAddress((void**)&sc,   g_sc);
    cudaGetSymbolAddress((void**)&pb,   g_pb);
    cudaGetSymbolAddress((void**)&at,   g_at);
    cudaGetSymbolAddress((void**)&ff,   g_ff);
    cudaGetSymbolAddress((void**)&wb,   g_wb);

    const int Mtok = BB * SQ;                     // 2048
    const long long TSZ = (long long)Mtok * DIM;  // 1,048,576
    bf16* q  = qkvb;
    bf16* k_ = qkvb + TSZ;
    bf16* vt = qkvb + 2 * TSZ;

    cudaFuncSetAttribute(bmma_k<M_QKV,    64>,  cudaFuncAttributeMaxDynamicSharedMemorySize, SMEM_BN64);
    cudaFuncSetAttribute(bmma_k<M_RESID,  64>,  cudaFuncAttributeMaxDynamicSharedMemorySize, SMEM_BN64);
    cudaFuncSetAttribute(bmma_k<M_PV,     64>,  cudaFuncAttributeMaxDynamicSharedMemorySize, SMEM_BN64);
    cudaFuncSetAttribute(bmma_k<M_SCORES, 128>, cudaFuncAttributeMaxDynamicSharedMemorySize, SMEM_BN128);
    cudaFuncSetAttribute(bmma_k<M_RELU,   128>, cudaFuncAttributeMaxDynamicSharedMemorySize, SMEM_BN128);
    cudaFuncSetAttribute(bmma_k<M_PLAIN,  128>, cudaFuncAttributeMaxDynamicSharedMemorySize, SMEM_BN128);

    // ---- weights -> bf16 scratch ----
    {
        const int nw1 = NL * DIM * DIM;
        const int nw2 = NL * DFF * DIM;
        const int nwg = NV * DIM;
        cvt_k<<<nw1 / 1024, 256>>>(Wq, wb + OFF_WQ, nw1);
        cvt_k<<<nw1 / 1024, 256>>>(Wk, wb + OFF_WK, nw1);
        cvt_k<<<nw1 / 1024, 256>>>(Wv, wb + OFF_WV, nw1);
        cvt_k<<<nw1 / 1024, 256>>>(Wo, wb + OFF_WO, nw1);
        cvt_k<<<nw2 / 1024, 256>>>(W1, wb + OFF_W1, nw2);
        cvt_k<<<nw2 / 1024, 256>>>(W2, wb + OFF_W2, nw2);
        cvt_k<<<nwg / 1024, 256>>>(Wg, wb + OFF_WG, nwg);
    }

    embed_k<<<Mtok, 256>>>(inp, emb, x);

    for (int l = 0; l < NL; ++l) {
        const long long wOff = (long long)l * DIM * DIM;
        const long long fOff = (long long)l * DFF * DIM;

        ln_k<<<Mtok, 256>>>(x, ln1a + l * DIM, ln1b + l * DIM, h);

        // fused QKV: z picks W/bias; q,k normal layout, v transposed
        {
            GP p = mkgp(h, wb + OFF_WQ + wOff, bq + l * DIM);
            p.B1 = wb + OFF_WK + wOff;  p.B2 = wb + OFF_WV + wOff;
            p.bias1 = bk + l * DIM;     p.bias2 = bv + l * DIM;
            p.Cb = qkvb; p.N = DIM; p.K = DIM;
            bmma_k<M_QKV, 64><<<dim3(DIM / 64, Mtok / 128, 3), 256, SMEM_BN64>>>(p);
        }

        relbias_k<<<BB * NH * SQ / 8, 256>>>(q, rel + (long long)l * NH * MAXS * DKH, rb);

        // scores = scale*(q·k) + r[k], masked (causal blocks skip GEMM)
        {
            GP p = mkgp(q, k_, nullptr);
            p.rbias = rb; p.mask = mask; p.C = sc;
            p.N = SQ; p.K = DKH;
            p.Az = (long long)SQ * DKH; p.Bz = (long long)SQ * DKH;
            p.Cz = (long long)SQ * SQ; p.scale = 0.125f;
            bmma_k<M_SCORES, 128><<<dim3(SQ / 128, SQ / 128, BB * NH), 256, SMEM_BN128>>>(p);
        }

        softmax_k<<<BB * NH * SQ, 256>>>(sc, pb);

        // attn = P @ V (vT layout, causal K-tile skip) -> at [B,S,D] bf16
        {
            GP p = mkgp(pb, vt, nullptr);
            p.Cb = at; p.N = DKH; p.K = SQ;
            p.Az = (long long)SQ * SQ; p.Bz = (long long)DKH * SQ;
            bmma_k<M_PV, 64><<<dim3(1, SQ / 128, BB * NH), 256, SMEM_BN64>>>(p);
        }

        // x = x + attn @ Wo^T + bo
        {
            GP p = mkgp(at, wb + OFF_WO + wOff, bo + l * DIM);
            p.resid = x; p.C = x; p.N = DIM; p.K = DIM;
            bmma_k<M_RESID, 64><<<dim3(DIM / 64, Mtok / 128, 1), 256, SMEM_BN64>>>(p);
        }

        ln_k<<<Mtok, 256>>>(x, ln2a + l * DIM, ln2b + l * DIM, h);

        // ffn = relu(h @ W1^T + b1) -> bf16
        {
            GP p = mkgp(h, wb + OFF_W1 + fOff, b1 + l * DFF);
            p.Cb = ff; p.N = DFF; p.K = DIM;
            bmma_k<M_RELU, 128><<<dim3(DFF / 128, Mtok / 128, 1), 256, SMEM_BN128>>>(p);
        }
        // x = x + ffn @ W2^T + b2
        {
            GP p = mkgp(ff, wb + OFF_W2 + fOff, b2 + l * DIM);
            p.resid = x; p.C = x; p.N = DIM; p.K = DFF;
            bmma_k<M_RESID, 64><<<dim3(DIM / 64, Mtok / 128, 1), 256, SMEM_BN64>>>(p);
        }
    }

    ln_k<<<Mtok, 256>>>(x, lnfa, lnfb, h);

    // logits = h @ Wg^T + bg -> d_out
    {
        GP p = mkgp(h, wb + OFF_WG, bg);
        p.C = out; p.N = NV; p.K = DIM;
        bmma_k<M_PLAIN, 128><<<dim3(NV / 128, Mtok / 128, 1), 256, SMEM_BN128>>>(p);
    }

    logsoftmax_k<<<Mtok, 256>>>(out);
}

// round 6
// speedup vs baseline: 4.6216x; 1.3099x over previous
#include <cuda_runtime.h>
#include <cuda_bf16.h>
#include <math.h>

// Problem constants
#define BB   2
#define SQ   1024
#define DIM  512
#define NH   8
#define DKH  64
#define NL   6
#define DFF  2048
#define NV   32000
#define MAXS 1025   // MAXSEQ+1

typedef unsigned int u32;
typedef __nv_bfloat16 bf16;

// ---------------- device scratch (no allocations allowed) ----------------
__device__ float g_x   [BB*SQ*DIM];
__device__ bf16  g_h   [BB*SQ*DIM];
__device__ bf16  g_qkvb[3*BB*SQ*DIM];   // q[B,H,S,DK], k[B,H,S,DK], vT[B,H,DK,S]
__device__ float g_rb  [BB*NH*SQ];
__device__ bf16  g_at  [BB*SQ*DIM];
__device__ bf16  g_ff  [BB*SQ*DFF];
__device__ bf16  g_wb  [35258368];      // all weights as bf16

#define OFF_WQ 0
#define OFF_WK 1572864
#define OFF_WV 3145728
#define OFF_WO 4718592
#define OFF_W1 6291456
#define OFF_W2 12582912
#define OFF_WG 18874368

// ======================= PTX helpers =======================
__device__ __forceinline__ u32 sm32(const void* p) {
    u32 a;
    asm("{ .reg .u64 t; cvta.to.shared.u64 t, %1; cvt.u32.u64 %0, t; }" : "=r"(a) : "l"(p));
    return a;
}
__device__ __forceinline__ void cp_async16(u32 s, const void* g) {
    asm volatile("cp.async.cg.shared.global [%0], [%1], 16;" :: "r"(s), "l"(g));
}
#define CP_COMMIT()  asm volatile("cp.async.commit_group;" ::: "memory")
#define CP_WAIT(N)   asm volatile("cp.async.wait_group " #N ";" ::: "memory")

#define LDSM4(r, addr) \
    asm volatile("ldmatrix.sync.aligned.m8n8.x4.shared.b16 {%0,%1,%2,%3}, [%4];" \
        : "=r"((r)[0]), "=r"((r)[1]), "=r"((r)[2]), "=r"((r)[3]) : "r"(addr))

__device__ __forceinline__ void mma16816(float* c, const u32* a, u32 b0, u32 b1) {
    asm volatile(
        "mma.sync.aligned.m16n8k16.row.col.f32.bf16.bf16.f32 "
        "{%0,%1,%2,%3},{%4,%5,%6,%7},{%8,%9},{%0,%1,%2,%3};"
        : "+f"(c[0]), "+f"(c[1]), "+f"(c[2]), "+f"(c[3])
        : "r"(a[0]), "r"(a[1]), "r"(a[2]), "r"(a[3]), "r"(b0), "r"(b1));
}
__device__ __forceinline__ u32 pack_bf(float lo, float hi) {
    __nv_bfloat162 t = __floats2bfloat162_rn(lo, hi);
    return *(u32*)&t;
}

// ======================= bf16 NT GEMM (ldmatrix + mma.m16n8k16) =======================
struct GP {
    const bf16* A; const bf16* B; const bf16* B1; const bf16* B2;
    const float* bias; const float* bias1; const float* bias2;
    const float* resid;
    float* C; bf16* Cb;
    int N, K;
};
enum { M_PLAIN = 0, M_QKV, M_RESID, M_RELU };

template<int MODE, int BN>
__global__ __launch_bounds__(256) void bmma_k(GP p) {
    constexpr int WN     = BN / 2;
    constexpr int NTN    = WN / 8;
    constexpr int NB16   = WN / 16;
    constexpr int ABYTES = 128 * 64;
    constexpr int BBYTES = BN * 64;
    constexpr int STG    = ABYTES + BBYTES;

    extern __shared__ char sm[];
    const u32 sb = sm32(sm);
    const int t = threadIdx.x, lane = t & 31, warp = t >> 5;
    const int wm = warp >> 1, wn = warp & 1;
    const int n0 = blockIdx.x * BN, m0 = blockIdx.y * 128, z = blockIdx.z;

    const bf16* A = p.A;
    const bf16* B; const float* bias;
    if (MODE == M_QKV) {
        B    = (z == 0) ? p.B : (z == 1 ? p.B1 : p.B2);
        bias = (z == 0) ? p.bias : (z == 1 ? p.bias1 : p.bias2);
    } else { B = p.B; bias = p.bias; }

    const int ntile = p.K >> 5;

    auto fill = [&](int it) {
        u32 ab = sb + (it & 3) * STG;
        u32 bb = ab + ABYTES;
        int k0 = it << 5;
        const bf16* Ag = A + (long long)m0 * p.K + k0;
        const bf16* Bg = B + (long long)n0 * p.K + k0;
#pragma unroll
        for (int i = 0; i < 2; ++i) {
            int idx = t + i * 256;
            int r = idx >> 2, c = idx & 3;
            cp_async16(ab + r * 64 + ((c ^ ((r >> 1) & 3)) << 4), Ag + (long long)r * p.K + c * 8);
        }
#pragma unroll
        for (int i = 0; i < BN / 64; ++i) {
            int idx = t + i * 256;
            int r = idx >> 2, c = idx & 3;
            cp_async16(bb + r * 64 + ((c ^ ((r >> 1) & 3)) << 4), Bg + (long long)r * p.K + c * 8);
        }
        CP_COMMIT();
    };

    float acc[2][NTN][4];
#pragma unroll
    for (int i = 0; i < 2; ++i)
#pragma unroll
        for (int j = 0; j < NTN; ++j)
#pragma unroll
            for (int c = 0; c < 4; ++c) acc[i][j][c] = 0.f;

    for (int s = 0; s < 3 && s < ntile; ++s) fill(s);

    for (int it = 0; it < ntile; ++it) {
        int w = ntile - it - 1; if (w > 2) w = 2;
        if (w == 2) { CP_WAIT(2); } else if (w == 1) { CP_WAIT(1); } else { CP_WAIT(0); }
        __syncthreads();
        if (it + 3 < ntile) fill(it + 3);

        u32 ab = sb + (it & 3) * STG;
        u32 bb = ab + ABYTES;
#pragma unroll
        for (int ks = 0; ks < 2; ++ks) {
            const int cc = ks * 2 + (lane >> 4);
            u32 a[2][4];
#pragma unroll
            for (int mt = 0; mt < 2; ++mt) {
                int mr = wm * 32 + mt * 16 + (lane & 7) + ((lane >> 3) & 1) * 8;
                LDSM4(a[mt], ab + mr * 64 + ((cc ^ ((mr >> 1) & 3)) << 4));
            }
#pragma unroll
            for (int nb = 0; nb < NB16; ++nb) {
                int nr = wn * WN + nb * 16 + (lane & 7) + ((lane >> 3) & 1) * 8;
                u32 b[4];
                LDSM4(b, bb + nr * 64 + ((cc ^ ((nr >> 1) & 3)) << 4));
#pragma unroll
                for (int mt = 0; mt < 2; ++mt) {
                    mma16816(acc[mt][2 * nb + 0], a[mt], b[0], b[2]);
                    mma16816(acc[mt][2 * nb + 1], a[mt], b[1], b[3]);
                }
            }
        }
    }

#pragma unroll
    for (int mt = 0; mt < 2; ++mt) {
#pragma unroll
        for (int nt = 0; nt < NTN; ++nt) {
#pragma unroll
            for (int c = 0; c < 4; ++c) {
                int m = m0 + wm * 32 + mt * 16 + (lane >> 2) + ((c >= 2) ? 8 : 0);
                int n = n0 + wn * WN + nt * 8 + 2 * (lane & 3) + (c & 1);
                float v = acc[mt][nt][c];
                if (MODE == M_PLAIN) {
                    p.C[(long long)m * p.N + n] = v + bias[n];
                } else if (MODE == M_QKV) {
                    float o = v + bias[n];
                    int b = m >> 10, s2 = m & (SQ - 1);
                    int hh = n >> 6, dk = n & 63;
                    long long TSZ = (long long)BB * SQ * DIM;
                    if (z < 2)
                        p.Cb[z * TSZ + (((long long)(b * NH + hh)) * SQ + s2) * DKH + dk] = __float2bfloat16_rn(o);
                    else
                        p.Cb[2 * TSZ + (((long long)(b * NH + hh)) * DKH + dk) * SQ + s2] = __float2bfloat16_rn(o);
                } else if (MODE == M_RESID) {
                    long long idx = (long long)m * p.N + n;
                    p.C[idx] = p.resid[idx] + v + bias[n];
                } else if (MODE == M_RELU) {
                    float o = v + bias[n];
                    p.Cb[(long long)m * p.N + n] = __float2bfloat16_rn(o > 0.f ? o : 0.f);
                }
            }
        }
    }
}

// ======================= fused flash attention =======================
// grid (8 q-blocks, 16 bh), 256 threads = 8 warps; warp owns 16 q rows.
// Q/K [B,H,S,DK] bf16, V as vT [B,H,DK,S] bf16; out at[B,S,DIM] bf16.
// Causal: key block range [0, qb]; diagonal masked by index; rb bias per key.
#define FA_QBYTES  16384
#define FA_KBYTES  16384
#define FA_VBYTES  16384
#define FA_STG     (FA_KBYTES + FA_VBYTES + 512)
#define FA_SMEM    (FA_QBYTES + 2 * FA_STG)

__global__ __launch_bounds__(256) void flash_k(const bf16* __restrict__ qg,
                                               const bf16* __restrict__ kg,
                                               const bf16* __restrict__ vg,
                                               const float* __restrict__ rbias,
                                               bf16* __restrict__ at) {
    extern __shared__ char sm[];
    const u32 sb = sm32(sm);
    const int t = threadIdx.x, lane = t & 31, warp = t >> 5;
    const int qb = blockIdx.x, z = blockIdx.y;
    const int b = z >> 3, h = z & 7;

    const bf16* Qg = qg + ((long long)z * SQ + qb * 128) * DKH;
    const bf16* Kg = kg + (long long)z * SQ * DKH;
    const bf16* Vg = vg + (long long)z * DKH * SQ;
    const float* rbg = rbias + (long long)z * SQ;

    const int nkb = qb + 1;

    // ---- Q tile: 128 rows x 64 dk (128B rows, XOR swizzle) ----
#pragma unroll
    for (int i = 0; i < 4; ++i) {
        int idx = t + i * 256;
        int r = idx >> 3, c = idx & 7;
        cp_async16(sb + r * 128 + ((c ^ (r & 7)) << 4), Qg + (long long)r * DKH + c * 8);
    }
    auto fillKV = [&](int kb) {
        u32 kbse = sb + FA_QBYTES + (kb & 1) * FA_STG;
        u32 vbse = kbse + FA_KBYTES;
        u32 rbse = vbse + FA_VBYTES;
        const bf16* Kt = Kg + (long long)kb * 128 * DKH;
        const bf16* Vt = Vg + kb * 128;
#pragma unroll
        for (int i = 0; i < 4; ++i) {       // K: 128 rows x 8 chunks
            int idx = t + i * 256;
            int r = idx >> 3, c = idx & 7;
            cp_async16(kbse + r * 128 + ((c ^ (r & 7)) << 4), Kt + (long long)r * DKH + c * 8);
        }
#pragma unroll
        for (int i = 0; i < 4; ++i) {       // V: 64 dk rows x 16 chunks (256B rows)
            int idx = t + i * 256;
            int r = idx >> 4, c = idx & 15;
            cp_async16(vbse + r * 256 + ((c ^ (r & 7)) << 4), Vt + (long long)r * SQ + c * 8);
        }
        if (t < 32) cp_async16(rbse + t * 16, rbg + kb * 128 + t * 4);
        CP_COMMIT();
    };
    fillKV(0);

    float o[8][4];
#pragma unroll
    for (int i = 0; i < 8; ++i)
#pragma unroll
        for (int c = 0; c < 4; ++c) o[i][c] = 0.f;
    float m0 = -1e30f, m1 = -1e30f, l0 = 0.f, l1 = 0.f;

    u32 aq[4][4];
    bool qloaded = false;

    for (int kb = 0; kb < nkb; ++kb) {
        CP_WAIT(0);
        __syncthreads();
        if (kb + 1 < nkb) fillKV(kb + 1);

        if (!qloaded) {
#pragma unroll
            for (int ks = 0; ks < 4; ++ks) {
                int mr = warp * 16 + (lane & 7) + ((lane >> 3) & 1) * 8;
                int cc = ks * 2 + (lane >> 4);
                LDSM4(aq[ks], sb + mr * 128 + ((cc ^ (mr & 7)) << 4));
            }
            qloaded = true;
        }

        u32 kbse = sb + FA_QBYTES + (kb & 1) * FA_STG;
        u32 vbse = kbse + FA_KBYTES;
        float* rbs = (float*)(sm + (kbse - sb) + FA_KBYTES + FA_VBYTES);

        // ---- S = Q K^T ----
        float s[16][4];
#pragma unroll
        for (int i = 0; i < 16; ++i)
#pragma unroll
            for (int c = 0; c < 4; ++c) s[i][c] = 0.f;
#pragma unroll
        for (int ks = 0; ks < 4; ++ks) {
            const int cc = ks * 2 + (lane >> 4);
#pragma unroll
            for (int np = 0; np < 8; ++np) {
                int nr = np * 16 + (lane & 7) + ((lane >> 3) & 1) * 8;
                u32 bfr[4];
                LDSM4(bfr, kbse + nr * 128 + ((cc ^ (nr & 7)) << 4));
                mma16816(s[2 * np + 0], aq[ks], bfr[0], bfr[2]);
                mma16816(s[2 * np + 1], aq[ks], bfr[1], bfr[3]);
            }
        }

        // ---- scale + rel bias + causal mask ----
        const int colq = 2 * (lane & 3);
        const int r0 = warp * 16 + (lane >> 2), r1 = r0 + 8;
#pragma unroll
        for (int nt = 0; nt < 16; ++nt) {
            float2 rb2 = *(float2*)(rbs + nt * 8 + colq);
            s[nt][0] = s[nt][0] * 0.125f + rb2.x;
            s[nt][1] = s[nt][1] * 0.125f + rb2.y;
            s[nt][2] = s[nt][2] * 0.125f + rb2.x;
            s[nt][3] = s[nt][3] * 0.125f + rb2.y;
        }
        if (kb == qb) {
#pragma unroll
            for (int nt = 0; nt < 16; ++nt) {
                int c0 = nt * 8 + colq;
                if (c0 > r0)     s[nt][0] = -1e30f;
                if (c0 + 1 > r0) s[nt][1] = -1e30f;
                if (c0 > r1)     s[nt][2] = -1e30f;
                if (c0 + 1 > r1) s[nt][3] = -1e30f;
            }
        }

        // ---- online softmax ----
        float mx0 = -1e30f, mx1 = -1e30f;
#pragma unroll
        for (int nt = 0; nt < 16; ++nt) {
            mx0 = fmaxf(mx0, fmaxf(s[nt][0], s[nt][1]));
            mx1 = fmaxf(mx1, fmaxf(s[nt][2], s[nt][3]));
        }
        mx0 = fmaxf(mx0, __shfl_xor_sync(0xffffffffu, mx0, 1));
        mx0 = fmaxf(mx0, __shfl_xor_sync(0xffffffffu, mx0, 2));
        mx1 = fmaxf(mx1, __shfl_xor_sync(0xffffffffu, mx1, 1));
        mx1 = fmaxf(mx1, __shfl_xor_sync(0xffffffffu, mx1, 2));
        float M0 = fmaxf(m0, mx0), M1 = fmaxf(m1, mx1);
        float a0 = expf(m0 - M0), a1 = expf(m1 - M1);
        float sum0 = 0.f, sum1 = 0.f;
#pragma unroll
        for (int nt = 0; nt < 16; ++nt) {
            s[nt][0] = expf(s[nt][0] - M0); sum0 += s[nt][0];
            s[nt][1] = expf(s[nt][1] - M0); sum0 += s[nt][1];
            s[nt][2] = expf(s[nt][2] - M1); sum1 += s[nt][2];
            s[nt][3] = expf(s[nt][3] - M1); sum1 += s[nt][3];
        }
        sum0 += __shfl_xor_sync(0xffffffffu, sum0, 1);
        sum0 += __shfl_xor_sync(0xffffffffu, sum0, 2);
        sum1 += __shfl_xor_sync(0xffffffffu, sum1, 1);
        sum1 += __shfl_xor_sync(0xffffffffu, sum1, 2);
        l0 = l0 * a0 + sum0;  l1 = l1 * a1 + sum1;
        m0 = M0;  m1 = M1;
#pragma unroll
        for (int i = 0; i < 8; ++i) {
            o[i][0] *= a0; o[i][1] *= a0; o[i][2] *= a1; o[i][3] *= a1;
        }

        // ---- O += P V ----
#pragma unroll
        for (int kv = 0; kv < 8; ++kv) {
            u32 pa[4];
            pa[0] = pack_bf(s[2 * kv][0],     s[2 * kv][1]);
            pa[1] = pack_bf(s[2 * kv][2],     s[2 * kv][3]);
            pa[2] = pack_bf(s[2 * kv + 1][0], s[2 * kv + 1][1]);
            pa[3] = pack_bf(s[2 * kv + 1][2], s[2 * kv + 1][3]);
            const int cc = kv * 2 + (lane >> 4);
#pragma unroll
            for (int nd = 0; nd < 4; ++nd) {
                int nr = nd * 16 + (lane & 7) + ((lane >> 3) & 1) * 8;
                u32 bfr[4];
                LDSM4(bfr, vbse + nr * 256 + ((cc ^ (nr & 7)) << 4));
                mma16816(o[2 * nd + 0], pa, bfr[0], bfr[2]);
                mma16816(o[2 * nd + 1], pa, bfr[1], bfr[3]);
            }
        }
        __syncthreads();
    }

    // ---- normalize + write out ----
    float inv0 = 1.f / l0, inv1 = 1.f / l1;
    const int r0 = qb * 128 + warp * 16 + (lane >> 2);
#pragma unroll
    for (int nd = 0; nd < 8; ++nd) {
        int n = h * DKH + nd * 8 + 2 * (lane & 3);
        __nv_bfloat162 v0 = __floats2bfloat162_rn(o[nd][0] * inv0, o[nd][1] * inv0);
        __nv_bfloat162 v1 = __floats2bfloat162_rn(o[nd][2] * inv1, o[nd][3] * inv1);
        *(__nv_bfloat162*)(at + ((long long)(b * SQ) + r0) * DIM + n)     = v0;
        *(__nv_bfloat162*)(at + ((long long)(b * SQ) + r0 + 8) * DIM + n) = v1;
    }
}

// ---------------- weight f32 -> bf16 conversion ----------------
__global__ void cvt_k(const float* s, bf16* d, int n) {
    int i = (blockIdx.x * 256 + threadIdx.x) * 4;
    if (i < n) {
        float4 v = *(const float4*)(s + i);
        d[i + 0] = __float2bfloat16_rn(v.x);
        d[i + 1] = __float2bfloat16_rn(v.y);
        d[i + 2] = __float2bfloat16_rn(v.z);
        d[i + 3] = __float2bfloat16_rn(v.w);
    }
}

// ---------------- embedding + sinusoidal PE ----------------
__global__ void embed_k(const int* inp, const float* emb, float* x) {
    int row = blockIdx.x;
    int s   = row & (SQ - 1);
    int tok = inp[row];
    const float* e = emb + (long long)tok * DIM;
    const float ln10k_over_d = 9.210340371976184f / (float)DIM;
    for (int d = threadIdx.x; d < DIM; d += 256) {
        int   i2  = d & ~1;
        float dv  = expf(-(float)i2 * ln10k_over_d);
        float arg = (float)s * dv;
        float pe  = (d & 1) ? cosf(arg) : sinf(arg);
        x[(long long)row * DIM + d] = e[d] * 22.62741699796952f + pe;
    }
}

// ---------------- layernorm (ddof=1, /(std+eps)), bf16 output ----------------
__global__ void ln_k(const float* x, const float* ga, const float* be, bf16* y) {
    int row = blockIdx.x;
    const float* xr = x + (long long)row * DIM;
    bf16* yr = y + (long long)row * DIM;
    __shared__ float red[256];
    int t = threadIdx.x;
    float v0 = xr[t], v1 = xr[t + 256];
    red[t] = v0 + v1;
    __syncthreads();
    for (int o = 128; o > 0; o >>= 1) { if (t < o) red[t] += red[t + o]; __syncthreads(); }
    float mean = red[0] * (1.f / (float)DIM);
    __syncthreads();
    float d0 = v0 - mean, d1 = v1 - mean;
    red[t] = d0 * d0 + d1 * d1;
    __syncthreads();
    for (int o = 128; o > 0; o >>= 1) { if (t < o) red[t] += red[t + o]; __syncthreads(); }
    float stdv = sqrtf(red[0] / (float)(DIM - 1));
    float inv  = 1.f / (stdv + 1e-6f);
    yr[t]       = __float2bfloat16_rn(ga[t] * d0 * inv + be[t]);
    yr[t + 256] = __float2bfloat16_rn(ga[t + 256] * d1 * inv + be[t + 256]);
}

// ---------------- relative bias: r[b,h,k] = scale * dot(q[b,h,k], pe[h,k]) ----
__global__ void relbias_k(const bf16* q, const float* rel, float* r) {
    int idx  = blockIdx.x * 8 + (threadIdx.x >> 5);
    int lane = threadIdx.x & 31;
    int k = idx & (SQ - 1);
    int h = (idx >> 10) & (NH - 1);
    const bf16*  qp = q   + (long long)idx * DKH;
    const float* pp = rel + ((long long)h * MAXS + k) * DKH;
    float d = __bfloat162float(qp[lane]) * pp[lane]
            + __bfloat162float(qp[lane + 32]) * pp[lane + 32];
    for (int o = 16; o > 0; o >>= 1) d += __shfl_xor_sync(0xffffffffu, d, o);
    if (lane == 0) r[idx] = d * 0.125f;
}

// ---------------- log_softmax over vocab (in place on d_out) ----------------
__global__ void logsoftmax_k(float* out) {
    float* r = out + (long long)blockIdx.x * NV;
    __shared__ float red[256];
    int t = threadIdx.x;
    float mx = -1e30f;
    for (int k = t; k < NV; k += 256) mx = fmaxf(mx, r[k]);
    red[t] = mx; __syncthreads();
    for (int o = 128; o > 0; o >>= 1) { if (t < o) red[t] = fmaxf(red[t], red[t + o]); __syncthreads(); }
    mx = red[0]; __syncthreads();
    float sum = 0.f;
    for (int k = t; k < NV; k += 256) sum += expf(r[k] - mx);
    red[t] = sum; __syncthreads();
    for (int o = 128; o > 0; o >>= 1) { if (t < o) red[t] += red[t + o]; __syncthreads(); }
    float lse = mx + logf(red[0]);
    __syncthreads();
    for (int k = t; k < NV; k += 256) r[k] -= lse;
}

// ---------------- host driver ----------------
#define SMEM_BN128 65536
#define SMEM_BN64  49152

static inline GP mkgp(const bf16* A, const bf16* B, const float* bias) {
    GP p; p.A = A; p.B = B; p.B1 = nullptr; p.B2 = nullptr;
    p.bias = bias; p.bias1 = nullptr; p.bias2 = nullptr;
    p.resid = nullptr; p.C = nullptr; p.Cb = nullptr;
    p.N = 0; p.K = 0;
    return p;
}

extern "C" void kernel_launch(void* const* d_in, const int* in_sizes, int n_in,
                              void* d_out, int out_size) {
    const int*   inp   = (const int*)  d_in[0];
    const float* emb   = (const float*)d_in[2];
    const float* Wq    = (const float*)d_in[3];
    const float* bq    = (const float*)d_in[4];
    const float* Wk    = (const float*)d_in[5];
    const float* bk    = (const float*)d_in[6];
    const float* Wv    = (const float*)d_in[7];
    const float* bv    = (const float*)d_in[8];
    const float* Wo    = (const float*)d_in[9];
    const float* bo    = (const float*)d_in[10];
    const float* rel   = (const float*)d_in[11];
    const float* ln1a  = (const float*)d_in[12];
    const float* ln1b  = (const float*)d_in[13];
    const float* ln2a  = (const float*)d_in[14];
    const float* ln2b  = (const float*)d_in[15];
    const float* W1    = (const float*)d_in[16];
    const float* b1    = (const float*)d_in[17];
    const float* W2    = (const float*)d_in[18];
    const float* b2    = (const float*)d_in[19];
    const float* lnfa  = (const float*)d_in[20];
    const float* lnfb  = (const float*)d_in[21];
    const float* Wg    = (const float*)d_in[22];
    const float* bg    = (const float*)d_in[23];
    float* out = (float*)d_out;

    float *x, *rb;
    bf16 *h, *qkvb, *at, *ff, *wb;
    cudaGetSymbolAddress((void**)&x,    g_x);
    cudaGetSymbolAddress((void**)&h,    g_h);
    cudaGetSymbolAddress((void**)&qkvb, g_qkvb);
    cudaGetSymbolAddress((void**)&rb,   g_rb);
    cudaGetSymbolAddress((void**)&at,   g_at);
    cudaGetSymbolAddress((void**)&ff,   g_ff);
    cudaGetSymbolAddress((void**)&wb,   g_wb);

    const int Mtok = BB * SQ;                     // 2048
    const long long TSZ = (long long)Mtok * DIM;  // 1,048,576
    bf16* q  = qkvb;
    bf16* k_ = qkvb + TSZ;
    bf16* vt = qkvb + 2 * TSZ;

    cudaFuncSetAttribute(bmma_k<M_QKV,   64>,  cudaFuncAttributeMaxDynamicSharedMemorySize, SMEM_BN64);
    cudaFuncSetAttribute(bmma_k<M_RESID, 64>,  cudaFuncAttributeMaxDynamicSharedMemorySize, SMEM_BN64);
    cudaFuncSetAttribute(bmma_k<M_RELU,  128>, cudaFuncAttributeMaxDynamicSharedMemorySize, SMEM_BN128);
    cudaFuncSetAttribute(bmma_k<M_PLAIN, 128>, cudaFuncAttributeMaxDynamicSharedMemorySize, SMEM_BN128);
    cudaFuncSetAttribute(flash_k, cudaFuncAttributeMaxDynamicSharedMemorySize, FA_SMEM);

    // ---- weights -> bf16 scratch ----
    {
        const int nw1 = NL * DIM * DIM;
        const int nw2 = NL * DFF * DIM;
        const int nwg = NV * DIM;
        cvt_k<<<nw1 / 1024, 256>>>(Wq, wb + OFF_WQ, nw1);
        cvt_k<<<nw1 / 1024, 256>>>(Wk, wb + OFF_WK, nw1);
        cvt_k<<<nw1 / 1024, 256>>>(Wv, wb + OFF_WV, nw1);
        cvt_k<<<nw1 / 1024, 256>>>(Wo, wb + OFF_WO, nw1);
        cvt_k<<<nw2 / 1024, 256>>>(W1, wb + OFF_W1, nw2);
        cvt_k<<<nw2 / 1024, 256>>>(W2, wb + OFF_W2, nw2);
        cvt_k<<<nwg / 1024, 256>>>(Wg, wb + OFF_WG, nwg);
    }

    embed_k<<<Mtok, 256>>>(inp, emb, x);

    for (int l = 0; l < NL; ++l) {
        const long long wOff = (long long)l * DIM * DIM;
        const long long fOff = (long long)l * DFF * DIM;

        ln_k<<<Mtok, 256>>>(x, ln1a + l * DIM, ln1b + l * DIM, h);

        // fused QKV: z picks W/bias; q,k normal layout, v transposed
        {
            GP p = mkgp(h, wb + OFF_WQ + wOff, bq + l * DIM);
            p.B1 = wb + OFF_WK + wOff;  p.B2 = wb + OFF_WV + wOff;
            p.bias1 = bk + l * DIM;     p.bias2 = bv + l * DIM;
            p.Cb = qkvb; p.N = DIM; p.K = DIM;
            bmma_k<M_QKV, 64><<<dim3(DIM / 64, Mtok / 128, 3), 256, SMEM_BN64>>>(p);
        }

        relbias_k<<<BB * NH * SQ / 8, 256>>>(q, rel + (long long)l * NH * MAXS * DKH, rb);

        // fused attention: scores + bias + causal mask + softmax + PV
        flash_k<<<dim3(SQ / 128, BB * NH), 256, FA_SMEM>>>(q, k_, vt, rb, at);

        // x = x + attn @ Wo^T + bo
        {
            GP p = mkgp(at, wb + OFF_WO + wOff, bo + l * DIM);
            p.resid = x; p.C = x; p.N = DIM; p.K = DIM;
            bmma_k<M_RESID, 64><<<dim3(DIM / 64, Mtok / 128, 1), 256, SMEM_BN64>>>(p);
        }

        ln_k<<<Mtok, 256>>>(x, ln2a + l * DIM, ln2b + l * DIM, h);

        // ffn = relu(h @ W1^T + b1) -> bf16
        {
            GP p = mkgp(h, wb + OFF_W1 + fOff, b1 + l * DFF);
            p.Cb = ff; p.N = DFF; p.K = DIM;
            bmma_k<M_RELU, 128><<<dim3(DFF / 128, Mtok / 128, 1), 256, SMEM_BN128>>>(p);
        }
        // x = x + ffn @ W2^T + b2
        {
            GP p = mkgp(ff, wb + OFF_W2 + fOff, b2 + l * DIM);
            p.resid = x; p.C = x; p.N = DIM; p.K = DFF;
            bmma_k<M_RESID, 64><<<dim3(DIM / 64, Mtok / 128, 1), 256, SMEM_BN64>>>(p);
        }
    }

    ln_k<<<Mtok, 256>>>(x, lnfa, lnfb, h);

    // logits = h @ Wg^T + bg -> d_out
    {
        GP p = mkgp(h, wb + OFF_WG, bg);
        p.C = out; p.N = NV; p.K = DIM;
        bmma_k<M_PLAIN, 128><<<dim3(NV / 128, Mtok / 128, 1), 256, SMEM_BN128>>>(p);
    }

    logsoftmax_k<<<Mtok, 256>>>(out);
}

// round 7
// speedup vs baseline: 5.4324x; 1.1754x over previous
#include <cuda_runtime.h>
#include <cuda_bf16.h>
#include <math.h>

// Problem constants
#define BB   2
#define SQ   1024
#define DIM  512
#define NH   8
#define DKH  64
#define NL   6
#define DFF  2048
#define NV   32000
#define MAXS 1025   // MAXSEQ+1

typedef unsigned int u32;
typedef __nv_bfloat16 bf16;

// ---------------- device scratch (no allocations allowed) ----------------
__device__ float g_x   [BB*SQ*DIM];
__device__ bf16  g_h   [BB*SQ*DIM];
__device__ bf16  g_qkvb[3*BB*SQ*DIM];   // q[B,H,S,DK], k[B,H,S,DK], vT[B,H,DK,S]
__device__ float g_rb  [BB*NH*SQ];
__device__ bf16  g_at  [BB*SQ*DIM];
__device__ bf16  g_ff  [BB*SQ*DFF];
__device__ bf16  g_wb  [35258368];      // all weights as bf16

#define OFF_WQ 0
#define OFF_WK 1572864
#define OFF_WV 3145728
#define OFF_WO 4718592
#define OFF_W1 6291456
#define OFF_W2 12582912
#define OFF_WG 18874368

// ======================= PTX helpers =======================
__device__ __forceinline__ u32 sm32(const void* p) {
    u32 a;
    asm("{ .reg .u64 t; cvta.to.shared.u64 t, %1; cvt.u32.u64 %0, t; }" : "=r"(a) : "l"(p));
    return a;
}
__device__ __forceinline__ void cp_async16(u32 s, const void* g) {
    asm volatile("cp.async.cg.shared.global [%0], [%1], 16;" :: "r"(s), "l"(g));
}
#define CP_COMMIT()  asm volatile("cp.async.commit_group;" ::: "memory")
#define CP_WAIT(N)   asm volatile("cp.async.wait_group " #N ";" ::: "memory")

#define LDSM4(r, addr) \
    asm volatile("ldmatrix.sync.aligned.m8n8.x4.shared.b16 {%0,%1,%2,%3}, [%4];" \
        : "=r"((r)[0]), "=r"((r)[1]), "=r"((r)[2]), "=r"((r)[3]) : "r"(addr))

__device__ __forceinline__ void mma16816(float* c, const u32* a, u32 b0, u32 b1) {
    asm volatile(
        "mma.sync.aligned.m16n8k16.row.col.f32.bf16.bf16.f32 "
        "{%0,%1,%2,%3},{%4,%5,%6,%7},{%8,%9},{%0,%1,%2,%3};"
        : "+f"(c[0]), "+f"(c[1]), "+f"(c[2]), "+f"(c[3])
        : "r"(a[0]), "r"(a[1]), "r"(a[2]), "r"(a[3]), "r"(b0), "r"(b1));
}
__device__ __forceinline__ u32 pack_bf(float lo, float hi) {
    __nv_bfloat162 t = __floats2bfloat162_rn(lo, hi);
    return *(u32*)&t;
}

// ======================= bf16 NT GEMM, BK=64, 3-stage =======================
// C[m,n] = sum_k A[m,k] * B[n,k]; both bf16 K-major. BM=128, BK=64 (128B rows,
// XOR swizzle), BN in {64,128}. 256 threads = 8 warps as 4(m) x 2(n).
struct GP {
    const bf16* A; const bf16* B; const bf16* B1; const bf16* B2;
    const float* bias; const float* bias1; const float* bias2;
    const float* resid;
    float* C; bf16* Cb;
    int N, K;
};
enum { M_PLAIN = 0, M_QKV, M_RESID, M_RELU };

#define GSMEM(BN) (3 * (16384 + (BN) * 128))

template<int MODE, int BN>
__global__ __launch_bounds__(256, 2) void bmma_k(GP p) {
    constexpr int WN     = BN / 2;
    constexpr int NTN    = WN / 8;
    constexpr int NB16   = WN / 16;
    constexpr int ABYTES = 128 * 128;
    constexpr int BBYTES = BN * 128;
    constexpr int STG    = ABYTES + BBYTES;

    extern __shared__ char sm[];
    const u32 sb = sm32(sm);
    const int t = threadIdx.x, lane = t & 31, warp = t >> 5;
    const int wm = warp >> 1, wn = warp & 1;
    const int n0 = blockIdx.x * BN, m0 = blockIdx.y * 128, z = blockIdx.z;

    const bf16* A = p.A;
    const bf16* B; const float* bias;
    if (MODE == M_QKV) {
        B    = (z == 0) ? p.B : (z == 1 ? p.B1 : p.B2);
        bias = (z == 0) ? p.bias : (z == 1 ? p.bias1 : p.bias2);
    } else { B = p.B; bias = p.bias; }

    const int ntile = p.K >> 6;

    auto fill = [&](int it) {
        u32 ab = sb + (it % 3) * STG;
        u32 bb = ab + ABYTES;
        int k0 = it << 6;
        const bf16* Ag = A + (long long)m0 * p.K + k0;
        const bf16* Bg = B + (long long)n0 * p.K + k0;
#pragma unroll
        for (int i = 0; i < 4; ++i) {               // A: 128 rows x 8 16B chunks
            int idx = t + i * 256;
            int r = idx >> 3, c = idx & 7;
            cp_async16(ab + r * 128 + ((c ^ (r & 7)) << 4), Ag + (long long)r * p.K + c * 8);
        }
#pragma unroll
        for (int i = 0; i < BN / 32; ++i) {         // B: BN rows x 8 16B chunks
            int idx = t + i * 256;
            int r = idx >> 3, c = idx & 7;
            cp_async16(bb + r * 128 + ((c ^ (r & 7)) << 4), Bg + (long long)r * p.K + c * 8);
        }
        CP_COMMIT();
    };

    float acc[2][NTN][4];
#pragma unroll
    for (int i = 0; i < 2; ++i)
#pragma unroll
        for (int j = 0; j < NTN; ++j)
#pragma unroll
            for (int c = 0; c < 4; ++c) acc[i][j][c] = 0.f;

    fill(0);
    if (1 < ntile) fill(1);

    for (int it = 0; it < ntile; ++it) {
        if (it + 1 < ntile) { CP_WAIT(1); } else { CP_WAIT(0); }
        __syncthreads();
        if (it + 2 < ntile) fill(it + 2);

        u32 ab = sb + (it % 3) * STG;
        u32 bb = ab + ABYTES;
#pragma unroll
        for (int ks = 0; ks < 4; ++ks) {
            const int cc = ks * 2 + (lane >> 4);
            u32 a[2][4];
#pragma unroll
            for (int mt = 0; mt < 2; ++mt) {
                int mr = wm * 32 + mt * 16 + (lane & 7) + ((lane >> 3) & 1) * 8;
                LDSM4(a[mt], ab + mr * 128 + ((cc ^ (mr & 7)) << 4));
            }
#pragma unroll
            for (int nb = 0; nb < NB16; ++nb) {
                int nr = wn * WN + nb * 16 + (lane & 7) + ((lane >> 3) & 1) * 8;
                u32 b[4];
                LDSM4(b, bb + nr * 128 + ((cc ^ (nr & 7)) << 4));
#pragma unroll
                for (int mt = 0; mt < 2; ++mt) {
                    mma16816(acc[mt][2 * nb + 0], a[mt], b[0], b[2]);
                    mma16816(acc[mt][2 * nb + 1], a[mt], b[1], b[3]);
                }
            }
        }
    }

    // ---- epilogue (paired stores where contiguous) ----
#pragma unroll
    for (int mt = 0; mt < 2; ++mt) {
#pragma unroll
        for (int nt = 0; nt < NTN; ++nt) {
            const int n  = n0 + wn * WN + nt * 8 + 2 * (lane & 3);
            const int mlo = m0 + wm * 32 + mt * 16 + (lane >> 2);
            float v0 = acc[mt][nt][0], v1 = acc[mt][nt][1];
            float v2 = acc[mt][nt][2], v3 = acc[mt][nt][3];
            if (MODE == M_PLAIN) {
                float b0 = bias[n], b1 = bias[n + 1];
                *(float2*)(p.C + (long long)mlo * p.N + n)       = make_float2(v0 + b0, v1 + b1);
                *(float2*)(p.C + (long long)(mlo + 8) * p.N + n) = make_float2(v2 + b0, v3 + b1);
            } else if (MODE == M_RESID) {
                float b0 = bias[n], b1 = bias[n + 1];
                long long i0 = (long long)mlo * p.N + n;
                long long i1 = (long long)(mlo + 8) * p.N + n;
                float2 r0 = *(float2*)(p.resid + i0), r1 = *(float2*)(p.resid + i1);
                *(float2*)(p.C + i0) = make_float2(r0.x + v0 + b0, r0.y + v1 + b1);
                *(float2*)(p.C + i1) = make_float2(r1.x + v2 + b0, r1.y + v3 + b1);
            } else if (MODE == M_RELU) {
                float b0 = bias[n], b1 = bias[n + 1];
                float o0 = v0 + b0, o1 = v1 + b1, o2 = v2 + b0, o3 = v3 + b1;
                o0 = o0 > 0.f ? o0 : 0.f; o1 = o1 > 0.f ? o1 : 0.f;
                o2 = o2 > 0.f ? o2 : 0.f; o3 = o3 > 0.f ? o3 : 0.f;
                *(__nv_bfloat162*)(p.Cb + (long long)mlo * p.N + n)       = __floats2bfloat162_rn(o0, o1);
                *(__nv_bfloat162*)(p.Cb + (long long)(mlo + 8) * p.N + n) = __floats2bfloat162_rn(o2, o3);
            } else if (MODE == M_QKV) {
                float b0 = bias[n], b1 = bias[n + 1];
                float o0 = v0 + b0, o1 = v1 + b1, o2 = v2 + b0, o3 = v3 + b1;
                const long long TSZ = (long long)BB * SQ * DIM;
                int hh = n >> 6, dk = n & 63;
#pragma unroll
                for (int half = 0; half < 2; ++half) {
                    int m = mlo + half * 8;
                    int b = m >> 10, s2 = m & (SQ - 1);
                    float e0 = half ? o2 : o0, e1 = half ? o3 : o1;
                    if (z < 2) {
                        *(__nv_bfloat162*)(p.Cb + z * TSZ + (((long long)(b * NH + hh)) * SQ + s2) * DKH + dk)
                            = __floats2bfloat162_rn(e0, e1);
                    } else {
                        bf16* base = p.Cb + 2 * TSZ + ((long long)(b * NH + hh)) * DKH * SQ + s2;
                        base[(long long)dk * SQ]       = __float2bfloat16_rn(e0);
                        base[(long long)(dk + 1) * SQ] = __float2bfloat16_rn(e1);
                    }
                }
            }
        }
    }
}

// ======================= fused flash attention =======================
#define FA_QBYTES  16384
#define FA_KBYTES  16384
#define FA_VBYTES  16384
#define FA_STG     (FA_KBYTES + FA_VBYTES + 512)
#define FA_SMEM    (FA_QBYTES + 2 * FA_STG)

__global__ __launch_bounds__(256) void flash_k(const bf16* __restrict__ qg,
                                               const bf16* __restrict__ kg,
                                               const bf16* __restrict__ vg,
                                               const float* __restrict__ rbias,
                                               bf16* __restrict__ at) {
    extern __shared__ char sm[];
    const u32 sb = sm32(sm);
    const int t = threadIdx.x, lane = t & 31, warp = t >> 5;
    const int qb = blockIdx.x, z = blockIdx.y;
    const int b = z >> 3, h = z & 7;

    const bf16* Qg = qg + ((long long)z * SQ + qb * 128) * DKH;
    const bf16* Kg = kg + (long long)z * SQ * DKH;
    const bf16* Vg = vg + (long long)z * DKH * SQ;
    const float* rbg = rbias + (long long)z * SQ;

    const int nkb = qb + 1;

#pragma unroll
    for (int i = 0; i < 4; ++i) {
        int idx = t + i * 256;
        int r = idx >> 3, c = idx & 7;
        cp_async16(sb + r * 128 + ((c ^ (r & 7)) << 4), Qg + (long long)r * DKH + c * 8);
    }
    auto fillKV = [&](int kb) {
        u32 kbse = sb + FA_QBYTES + (kb & 1) * FA_STG;
        u32 vbse = kbse + FA_KBYTES;
        u32 rbse = vbse + FA_VBYTES;
        const bf16* Kt = Kg + (long long)kb * 128 * DKH;
        const bf16* Vt = Vg + kb * 128;
#pragma unroll
        for (int i = 0; i < 4; ++i) {
            int idx = t + i * 256;
            int r = idx >> 3, c = idx & 7;
            cp_async16(kbse + r * 128 + ((c ^ (r & 7)) << 4), Kt + (long long)r * DKH + c * 8);
        }
#pragma unroll
        for (int i = 0; i < 4; ++i) {
            int idx = t + i * 256;
            int r = idx >> 4, c = idx & 15;
            cp_async16(vbse + r * 256 + ((c ^ (r & 7)) << 4), Vt + (long long)r * SQ + c * 8);
        }
        if (t < 32) cp_async16(rbse + t * 16, rbg + kb * 128 + t * 4);
        CP_COMMIT();
    };
    fillKV(0);

    float o[8][4];
#pragma unroll
    for (int i = 0; i < 8; ++i)
#pragma unroll
        for (int c = 0; c < 4; ++c) o[i][c] = 0.f;
    float m0 = -1e30f, m1 = -1e30f, l0 = 0.f, l1 = 0.f;

    u32 aq[4][4];
    bool qloaded = false;

    for (int kb = 0; kb < nkb; ++kb) {
        CP_WAIT(0);
        __syncthreads();
        if (kb + 1 < nkb) fillKV(kb + 1);

        if (!qloaded) {
#pragma unroll
            for (int ks = 0; ks < 4; ++ks) {
                int mr = warp * 16 + (lane & 7) + ((lane >> 3) & 1) * 8;
                int cc = ks * 2 + (lane >> 4);
                LDSM4(aq[ks], sb + mr * 128 + ((cc ^ (mr & 7)) << 4));
            }
            qloaded = true;
        }

        u32 kbse = sb + FA_QBYTES + (kb & 1) * FA_STG;
        u32 vbse = kbse + FA_KBYTES;
        float* rbs = (float*)(sm + (kbse - sb) + FA_KBYTES + FA_VBYTES);

        float s[16][4];
#pragma unroll
        for (int i = 0; i < 16; ++i)
#pragma unroll
            for (int c = 0; c < 4; ++c) s[i][c] = 0.f;
#pragma unroll
        for (int ks = 0; ks < 4; ++ks) {
            const int cc = ks * 2 + (lane >> 4);
#pragma unroll
            for (int np = 0; np < 8; ++np) {
                int nr = np * 16 + (lane & 7) + ((lane >> 3) & 1) * 8;
                u32 bfr[4];
                LDSM4(bfr, kbse + nr * 128 + ((cc ^ (nr & 7)) << 4));
                mma16816(s[2 * np + 0], aq[ks], bfr[0], bfr[2]);
                mma16816(s[2 * np + 1], aq[ks], bfr[1], bfr[3]);
            }
        }

        const int colq = 2 * (lane & 3);
        const int r0 = warp * 16 + (lane >> 2), r1 = r0 + 8;
#pragma unroll
        for (int nt = 0; nt < 16; ++nt) {
            float2 rb2 = *(float2*)(rbs + nt * 8 + colq);
            s[nt][0] = s[nt][0] * 0.125f + rb2.x;
            s[nt][1] = s[nt][1] * 0.125f + rb2.y;
            s[nt][2] = s[nt][2] * 0.125f + rb2.x;
            s[nt][3] = s[nt][3] * 0.125f + rb2.y;
        }
        if (kb == qb) {
#pragma unroll
            for (int nt = 0; nt < 16; ++nt) {
                int c0 = nt * 8 + colq;
                if (c0 > r0)     s[nt][0] = -1e30f;
                if (c0 + 1 > r0) s[nt][1] = -1e30f;
                if (c0 > r1)     s[nt][2] = -1e30f;
                if (c0 + 1 > r1) s[nt][3] = -1e30f;
            }
        }

        float mx0 = -1e30f, mx1 = -1e30f;
#pragma unroll
        for (int nt = 0; nt < 16; ++nt) {
            mx0 = fmaxf(mx0, fmaxf(s[nt][0], s[nt][1]));
            mx1 = fmaxf(mx1, fmaxf(s[nt][2], s[nt][3]));
        }
        mx0 = fmaxf(mx0, __shfl_xor_sync(0xffffffffu, mx0, 1));
        mx0 = fmaxf(mx0, __shfl_xor_sync(0xffffffffu, mx0, 2));
        mx1 = fmaxf(mx1, __shfl_xor_sync(0xffffffffu, mx1, 1));
        mx1 = fmaxf(mx1, __shfl_xor_sync(0xffffffffu, mx1, 2));
        float M0 = fmaxf(m0, mx0), M1 = fmaxf(m1, mx1);
        float a0 = expf(m0 - M0), a1 = expf(m1 - M1);
        float sum0 = 0.f, sum1 = 0.f;
#pragma unroll
        for (int nt = 0; nt < 16; ++nt) {
            s[nt][0] = expf(s[nt][0] - M0); sum0 += s[nt][0];
            s[nt][1] = expf(s[nt][1] - M0); sum0 += s[nt][1];
            s[nt][2] = expf(s[nt][2] - M1); sum1 += s[nt][2];
            s[nt][3] = expf(s[nt][3] - M1); sum1 += s[nt][3];
        }
        sum0 += __shfl_xor_sync(0xffffffffu, sum0, 1);
        sum0 += __shfl_xor_sync(0xffffffffu, sum0, 2);
        sum1 += __shfl_xor_sync(0xffffffffu, sum1, 1);
        sum1 += __shfl_xor_sync(0xffffffffu, sum1, 2);
        l0 = l0 * a0 + sum0;  l1 = l1 * a1 + sum1;
        m0 = M0;  m1 = M1;
#pragma unroll
        for (int i = 0; i < 8; ++i) {
            o[i][0] *= a0; o[i][1] *= a0; o[i][2] *= a1; o[i][3] *= a1;
        }

#pragma unroll
        for (int kv = 0; kv < 8; ++kv) {
            u32 pa[4];
            pa[0] = pack_bf(s[2 * kv][0],     s[2 * kv][1]);
            pa[1] = pack_bf(s[2 * kv][2],     s[2 * kv][3]);
            pa[2] = pack_bf(s[2 * kv + 1][0], s[2 * kv + 1][1]);
            pa[3] = pack_bf(s[2 * kv + 1][2], s[2 * kv + 1][3]);
            const int cc = kv * 2 + (lane >> 4);
#pragma unroll
            for (int nd = 0; nd < 4; ++nd) {
                int nr = nd * 16 + (lane & 7) + ((lane >> 3) & 1) * 8;
                u32 bfr[4];
                LDSM4(bfr, vbse + nr * 256 + ((cc ^ (nr & 7)) << 4));
                mma16816(o[2 * nd + 0], pa, bfr[0], bfr[2]);
                mma16816(o[2 * nd + 1], pa, bfr[1], bfr[3]);
            }
        }
        __syncthreads();
    }

    float inv0 = 1.f / l0, inv1 = 1.f / l1;
    const int r0 = qb * 128 + warp * 16 + (lane >> 2);
#pragma unroll
    for (int nd = 0; nd < 8; ++nd) {
        int n = h * DKH + nd * 8 + 2 * (lane & 3);
        __nv_bfloat162 v0 = __floats2bfloat162_rn(o[nd][0] * inv0, o[nd][1] * inv0);
        __nv_bfloat162 v1 = __floats2bfloat162_rn(o[nd][2] * inv1, o[nd][3] * inv1);
        *(__nv_bfloat162*)(at + ((long long)(b * SQ) + r0) * DIM + n)     = v0;
        *(__nv_bfloat162*)(at + ((long long)(b * SQ) + r0 + 8) * DIM + n) = v1;
    }
}

// ---------------- merged weight f32 -> bf16 conversion ----------------
struct CvtAll { const float* s[7]; bf16* d[7]; int cum[8]; };
__global__ __launch_bounds__(256) void cvtall_k(CvtAll j) {
    int g = blockIdx.x * 256 + threadIdx.x;   // float4 index
    if (g >= j.cum[7]) return;
    int seg = 0;
#pragma unroll
    for (int i = 1; i < 7; ++i) seg += (g >= j.cum[i]);
    int local = g - j.cum[seg];
    float4 v = ((const float4*)j.s[seg])[local];
    __nv_bfloat162* d2 = (__nv_bfloat162*)j.d[seg] + (long long)local * 2;
    d2[0] = __floats2bfloat162_rn(v.x, v.y);
    d2[1] = __floats2bfloat162_rn(v.z, v.w);
}

// ---------------- embedding + sinusoidal PE ----------------
__global__ void embed_k(const int* inp, const float* emb, float* x) {
    int row = blockIdx.x;
    int s   = row & (SQ - 1);
    int tok = inp[row];
    const float* e = emb + (long long)tok * DIM;
    const float ln10k_over_d = 9.210340371976184f / (float)DIM;
    for (int d = threadIdx.x; d < DIM; d += 256) {
        int   i2  = d & ~1;
        float dv  = expf(-(float)i2 * ln10k_over_d);
        float arg = (float)s * dv;
        float pe  = (d & 1) ? cosf(arg) : sinf(arg);
        x[(long long)row * DIM + d] = e[d] * 22.62741699796952f + pe;
    }
}

// ---------------- layernorm (ddof=1, /(std+eps)), bf16 output ----------------
__global__ void ln_k(const float* x, const float* ga, const float* be, bf16* y) {
    int row = blockIdx.x;
    const float* xr = x + (long long)row * DIM;
    bf16* yr = y + (long long)row * DIM;
    __shared__ float red[256];
    int t = threadIdx.x;
    float v0 = xr[t], v1 = xr[t + 256];
    red[t] = v0 + v1;
    __syncthreads();
    for (int o = 128; o > 0; o >>= 1) { if (t < o) red[t] += red[t + o]; __syncthreads(); }
    float mean = red[0] * (1.f / (float)DIM);
    __syncthreads();
    float d0 = v0 - mean, d1 = v1 - mean;
    red[t] = d0 * d0 + d1 * d1;
    __syncthreads();
    for (int o = 128; o > 0; o >>= 1) { if (t < o) red[t] += red[t + o]; __syncthreads(); }
    float stdv = sqrtf(red[0] / (float)(DIM - 1));
    float inv  = 1.f / (stdv + 1e-6f);
    yr[t]       = __float2bfloat16_rn(ga[t] * d0 * inv + be[t]);
    yr[t + 256] = __float2bfloat16_rn(ga[t + 256] * d1 * inv + be[t + 256]);
}

// ---------------- relative bias: r[b,h,k] = scale * dot(q[b,h,k], pe[h,k]) ----
__global__ void relbias_k(const bf16* q, const float* rel, float* r) {
    int idx  = blockIdx.x * 8 + (threadIdx.x >> 5);
    int lane = threadIdx.x & 31;
    int k = idx & (SQ - 1);
    int h = (idx >> 10) & (NH - 1);
    const bf16*  qp = q   + (long long)idx * DKH;
    const float* pp = rel + ((long long)h * MAXS + k) * DKH;
    float d = __bfloat162float(qp[lane]) * pp[lane]
            + __bfloat162float(qp[lane + 32]) * pp[lane + 32];
    for (int o = 16; o > 0; o >>= 1) d += __shfl_xor_sync(0xffffffffu, d, o);
    if (lane == 0) r[idx] = d * 0.125f;
}

// ---------------- log_softmax: smem row cache, 2 DRAM passes ----------------
#define LS_SMEM (NV * 4 + 2048)
__global__ __launch_bounds__(512) void logsoftmax_k(float* out) {
    extern __shared__ float row[];           // NV floats + 512 reduction
    float* red = row + NV;
    float* r = out + (long long)blockIdx.x * NV;
    int t = threadIdx.x;
    float mx = -1e30f;
    for (int k = t * 4; k < NV; k += 2048) {
        float4 v = *(const float4*)(r + k);
        *(float4*)(row + k) = v;
        mx = fmaxf(mx, fmaxf(fmaxf(v.x, v.y), fmaxf(v.z, v.w)));
    }
    red[t] = mx; __syncthreads();
    for (int o = 256; o > 0; o >>= 1) { if (t < o) red[t] = fmaxf(red[t], red[t + o]); __syncthreads(); }
    mx = red[0]; __syncthreads();
    float sum = 0.f;
    for (int k = t * 4; k < NV; k += 2048) {
        float4 v = *(const float4*)(row + k);
        sum += expf(v.x - mx) + expf(v.y - mx) + expf(v.z - mx) + expf(v.w - mx);
    }
    red[t] = sum; __syncthreads();
    for (int o = 256; o > 0; o >>= 1) { if (t < o) red[t] += red[t + o]; __syncthreads(); }
    float lse = mx + logf(red[0]);
    for (int k = t * 4; k < NV; k += 2048) {
        float4 v = *(const float4*)(row + k);
        v.x -= lse; v.y -= lse; v.z -= lse; v.w -= lse;
        *(float4*)(r + k) = v;
    }
}

// ---------------- host driver ----------------
static inline GP mkgp(const bf16* A, const bf16* B, const float* bias) {
    GP p; p.A = A; p.B = B; p.B1 = nullptr; p.B2 = nullptr;
    p.bias = bias; p.bias1 = nullptr; p.bias2 = nullptr;
    p.resid = nullptr; p.C = nullptr; p.Cb = nullptr;
    p.N = 0; p.K = 0;
    return p;
}

extern "C" void kernel_launch(void* const* d_in, const int* in_sizes, int n_in,
                              void* d_out, int out_size) {
    const int*   inp   = (const int*)  d_in[0];
    const float* emb   = (const float*)d_in[2];
    const float* Wq    = (const float*)d_in[3];
    const float* bq    = (const float*)d_in[4];
    const float* Wk    = (const float*)d_in[5];
    const float* bk    = (const float*)d_in[6];
    const float* Wv    = (const float*)d_in[7];
    const float* bv    = (const float*)d_in[8];
    const float* Wo    = (const float*)d_in[9];
    const float* bo    = (const float*)d_in[10];
    const float* rel   = (const float*)d_in[11];
    const float* ln1a  = (const float*)d_in[12];
    const float* ln1b  = (const float*)d_in[13];
    const float* ln2a  = (const float*)d_in[14];
    const float* ln2b  = (const float*)d_in[15];
    const float* W1    = (const float*)d_in[16];
    const float* b1    = (const float*)d_in[17];
    const float* W2    = (const float*)d_in[18];
    const float* b2    = (const float*)d_in[19];
    const float* lnfa  = (const float*)d_in[20];
    const float* lnfb  = (const float*)d_in[21];
    const float* Wg    = (const float*)d_in[22];
    const float* bg    = (const float*)d_in[23];
    float* out = (float*)d_out;

    float *x, *rb;
    bf16 *h, *qkvb, *at, *ff, *wb;
    cudaGetSymbolAddress((void**)&x,    g_x);
    cudaGetSymbolAddress((void**)&h,    g_h);
    cudaGetSymbolAddress((void**)&qkvb, g_qkvb);
    cudaGetSymbolAddress((void**)&rb,   g_rb);
    cudaGetSymbolAddress((void**)&at,   g_at);
    cudaGetSymbolAddress((void**)&ff,   g_ff);
    cudaGetSymbolAddress((void**)&wb,   g_wb);

    const int Mtok = BB * SQ;                     // 2048
    const long long TSZ = (long long)Mtok * DIM;  // 1,048,576
    bf16* q  = qkvb;
    bf16* k_ = qkvb + TSZ;
    bf16* vt = qkvb + 2 * TSZ;

    cudaFuncSetAttribute(bmma_k<M_QKV,   64>,  cudaFuncAttributeMaxDynamicSharedMemorySize, GSMEM(64));
    cudaFuncSetAttribute(bmma_k<M_RESID, 64>,  cudaFuncAttributeMaxDynamicSharedMemorySize, GSMEM(64));
    cudaFuncSetAttribute(bmma_k<M_RELU,  128>, cudaFuncAttributeMaxDynamicSharedMemorySize, GSMEM(128));
    cudaFuncSetAttribute(bmma_k<M_PLAIN, 128>, cudaFuncAttributeMaxDynamicSharedMemorySize, GSMEM(128));
    cudaFuncSetAttribute(flash_k,      cudaFuncAttributeMaxDynamicSharedMemorySize, FA_SMEM);
    cudaFuncSetAttribute(logsoftmax_k, cudaFuncAttributeMaxDynamicSharedMemorySize, LS_SMEM);

    // ---- all weights -> bf16 in one launch ----
    {
        const int n1 = NL * DIM * DIM / 4;    // 393216 float4s
        const int n2 = NL * DFF * DIM / 4;    // 1572864
        const int ng = NV * DIM / 4;          // 4096000
        CvtAll j;
        j.s[0] = Wq; j.s[1] = Wk; j.s[2] = Wv; j.s[3] = Wo; j.s[4] = W1; j.s[5] = W2; j.s[6] = Wg;
        j.d[0] = wb + OFF_WQ; j.d[1] = wb + OFF_WK; j.d[2] = wb + OFF_WV; j.d[3] = wb + OFF_WO;
        j.d[4] = wb + OFF_W1; j.d[5] = wb + OFF_W2; j.d[6] = wb + OFF_WG;
        j.cum[0] = 0;
        j.cum[1] = n1; j.cum[2] = 2 * n1; j.cum[3] = 3 * n1; j.cum[4] = 4 * n1;
        j.cum[5] = 4 * n1 + n2; j.cum[6] = 4 * n1 + 2 * n2; j.cum[7] = 4 * n1 + 2 * n2 + ng;
        cvtall_k<<<(j.cum[7] + 255) / 256, 256>>>(j);
    }

    embed_k<<<Mtok, 256>>>(inp, emb, x);

    for (int l = 0; l < NL; ++l) {
        const long long wOff = (long long)l * DIM * DIM;
        const long long fOff = (long long)l * DFF * DIM;

        ln_k<<<Mtok, 256>>>(x, ln1a + l * DIM, ln1b + l * DIM, h);

        // fused QKV: z picks W/bias; q,k normal layout, v transposed
        {
            GP p = mkgp(h, wb + OFF_WQ + wOff, bq + l * DIM);
            p.B1 = wb + OFF_WK + wOff;  p.B2 = wb + OFF_WV + wOff;
            p.bias1 = bk + l * DIM;     p.bias2 = bv + l * DIM;
            p.Cb = qkvb; p.N = DIM; p.K = DIM;
            bmma_k<M_QKV, 64><<<dim3(DIM / 64, Mtok / 128, 3), 256, GSMEM(64)>>>(p);
        }

        relbias_k<<<BB * NH * SQ / 8, 256>>>(q, rel + (long long)l * NH * MAXS * DKH, rb);

        // fused attention
        flash_k<<<dim3(SQ / 128, BB * NH), 256, FA_SMEM>>>(q, k_, vt, rb, at);

        // x = x + attn @ Wo^T + bo
        {
            GP p = mkgp(at, wb + OFF_WO + wOff, bo + l * DIM);
            p.resid = x; p.C = x; p.N = DIM; p.K = DIM;
            bmma_k<M_RESID, 64><<<dim3(DIM / 64, Mtok / 128, 1), 256, GSMEM(64)>>>(p);
        }

        ln_k<<<Mtok, 256>>>(x, ln2a + l * DIM, ln2b + l * DIM, h);

        // ffn = relu(h @ W1^T + b1) -> bf16
        {
            GP p = mkgp(h, wb + OFF_W1 + fOff, b1 + l * DFF);
            p.Cb = ff; p.N = DFF; p.K = DIM;
            bmma_k<M_RELU, 128><<<dim3(DFF / 128, Mtok / 128, 1), 256, GSMEM(128)>>>(p);
        }
        // x = x + ffn @ W2^T + b2
        {
            GP p = mkgp(ff, wb + OFF_W2 + fOff, b2 + l * DIM);
            p.resid = x; p.C = x; p.N = DIM; p.K = DFF;
            bmma_k<M_RESID, 64><<<dim3(DIM / 64, Mtok / 128, 1), 256, GSMEM(64)>>>(p);
        }
    }

    ln_k<<<Mtok, 256>>>(x, lnfa, lnfb, h);

    // logits = h @ Wg^T + bg -> d_out
    {
        GP p = mkgp(h, wb + OFF_WG, bg);
        p.C = out; p.N = NV; p.K = DIM;
        bmma_k<M_PLAIN, 128><<<dim3(NV / 128, Mtok / 128, 1), 256, GSMEM(128)>>>(p);
    }

    logsoftmax_k<<<Mtok, 512, LS_SMEM>>>(out);
}